// round 10
// baseline (speedup 1.0000x reference)
#include <cuda_runtime.h>
#include <cuda_bf16.h>
#include <cstdint>
#include <math.h>

#define BB 4
#define LSEQ 2048
#define DMODEL 1024
#define DINNER 2048
#define DSTATE 16
#define DTRANK 128
#define XPDIM 160
#define MTOT (BB*LSEQ)      // 8192

// ---------------- scratch ----------------------------------------------------
static __device__ float g_xr  [(size_t)MTOT * 2 * DINNER];
static __device__ float g_xc  [(size_t)MTOT * DINNER];
static __device__ float g_xdbl[(size_t)MTOT * XPDIM];
static __device__ float g_dlt [(size_t)MTOT * DINNER];
static __device__ float g_z   [(size_t)MTOT * DINNER];
static __device__ float g_xt  [(size_t)MTOT * DMODEL];
static __device__ float g_ipt [(size_t)2*DINNER * DMODEL];
static __device__ float g_xpt [(size_t)XPDIM * DINNER];
static __device__ float g_dpt [(size_t)DINNER * DTRANK];
static __device__ float g_opt [(size_t)DMODEL * DINNER];

// ---------------- PTX helpers ------------------------------------------------
__device__ __forceinline__ uint32_t smem_u32(const void* p) {
    uint32_t a;
    asm("{ .reg .u64 t; cvta.to.shared.u64 t, %1; cvt.u32.u64 %0, t; }" : "=r"(a) : "l"(p));
    return a;
}
__device__ __forceinline__ void cpa16(uint32_t s, const void* g) {
    asm volatile("cp.async.cg.shared.global [%0], [%1], 16;" :: "r"(s), "l"(g));
}
#define CP_COMMIT() asm volatile("cp.async.commit_group;" ::: "memory")
#define CP_WAIT(n)  asm volatile("cp.async.wait_group %0;" :: "n"(n) : "memory")

__device__ __forceinline__ void ldsm4(uint32_t* r, uint32_t a) {
    asm volatile("ldmatrix.sync.aligned.m8n8.x4.shared.b16 {%0,%1,%2,%3}, [%4];"
                 : "=r"(r[0]), "=r"(r[1]), "=r"(r[2]), "=r"(r[3]) : "r"(a));
}
__device__ __forceinline__ void mma1688(float* d, const uint32_t* a, const uint32_t* b) {
    asm volatile(
        "mma.sync.aligned.m16n8k8.row.col.f32.tf32.tf32.f32 "
        "{%0,%1,%2,%3}, {%4,%5,%6,%7}, {%8,%9}, {%0,%1,%2,%3};"
        : "+f"(d[0]), "+f"(d[1]), "+f"(d[2]), "+f"(d[3])
        : "r"(a[0]), "r"(a[1]), "r"(a[2]), "r"(a[3]), "r"(b[0]), "r"(b[1]));
}
__device__ __forceinline__ float rtf(float v) {
    uint32_t r;
    asm("cvt.rna.tf32.f32 %0, %1;" : "=r"(r) : "f"(v));
    return __uint_as_float(r);
}

// vectorized tf32 rounding pass
__global__ void round_k(const float4* __restrict__ in, float4* __restrict__ out, int n4) {
    int i = blockIdx.x * blockDim.x + threadIdx.x;
    if (i < n4) {
        float4 v = in[i];
        v.x = rtf(v.x); v.y = rtf(v.y); v.z = rtf(v.z); v.w = rtf(v.w);
        out[i] = v;
    }
}

// ---------------- tf32 HMMA GEMM: BK=32, 3-stage ring, fused-B ldsm4 ---------
template<int BM, int BN, int WARPS_M, int WARPS_N, int EPI, int RND>
__global__ void __launch_bounds__(WARPS_M * WARPS_N * 32)
gemm_tf(const float* __restrict__ A, int lda,
        const float* __restrict__ B, int ldb,
        float* __restrict__ C, int ldc, const float* __restrict__ bias, int K)
{
    constexpr int NT = WARPS_M * WARPS_N * 32;
    constexpr int RS = 144;                 // 32 floats (128B) + 16B pad
    constexpr int SA = BM * RS;
    constexpr int SB = BN * RS;
    constexpr int STAGE = SA + SB;
    constexpr int WM = BM / WARPS_M, WN = BN / WARPS_N;
    constexpr int IM = WM / 16, JN = WN / 8;

    extern __shared__ char smem[];
    const uint32_t sbase = smem_u32(smem);
    const int tid = threadIdx.x;
    const int warp = tid >> 5, lane = tid & 31;
    const int wm0 = (warp / WARPS_N) * WM;
    const int wn0 = (warp % WARPS_N) * WN;
    const int m0 = blockIdx.y * BM, n0 = blockIdx.x * BN;
    const int NC = K >> 5;

    float acc[IM][JN][4];
#pragma unroll
    for (int i = 0; i < IM; i++)
#pragma unroll
        for (int j = 0; j < JN; j++)
#pragma unroll
            for (int q = 0; q < 4; q++) acc[i][j][q] = 0.f;

    auto load_chunk = [&](int kc, int buf) {
        const int k0 = kc << 5;
        const uint32_t st = sbase + buf * STAGE;
        for (int idx = tid; idx < BM * 8; idx += NT) {
            int r = idx >> 3, c = idx & 7;
            cpa16(st + (uint32_t)(r * RS + c * 16), A + (size_t)(m0 + r) * lda + k0 + c * 4);
        }
        for (int idx = tid; idx < BN * 8; idx += NT) {
            int r = idx >> 3, c = idx & 7;
            cpa16(st + SA + (uint32_t)(r * RS + c * 16), B + (size_t)(n0 + r) * ldb + k0 + c * 4);
        }
        CP_COMMIT();
    };

    const uint32_t a_row  = (uint32_t)(wm0 + (lane & 15));
    const uint32_t a_half = (uint32_t)((lane >> 4) * 16);
    const uint32_t b_row  = (uint32_t)(wn0 + (lane & 7));
    const uint32_t b_sel  = (uint32_t)(((lane >> 3) & 3) * 16);  // 4 quadrants: ks:{b0,b1}, ks+1:{b0,b1}

    // 3-stage ring
    load_chunk(0, 0);
    if (NC > 1) load_chunk(1, 1);

    int buf = 0;
    for (int i = 0; i < NC; i++) {
        if (i + 1 < NC) CP_WAIT(1); else CP_WAIT(0);
        __syncthreads();
        if (i + 2 < NC) load_chunk(i + 2, (buf + 2 >= 3) ? buf - 1 : buf + 2);

        const uint32_t st = sbase + buf * STAGE;
#pragma unroll
        for (int kp = 0; kp < 2; kp++) {            // pairs of K8 steps
            uint32_t bq[JN][4];
#pragma unroll
            for (int jn = 0; jn < JN; jn++)          // one ldsm4 covers BOTH K8 steps
                ldsm4(bq[jn], st + SA + (b_row + jn * 8) * RS + kp * 64 + b_sel);
#pragma unroll
            for (int h = 0; h < 2; h++) {            // ks = kp*2 + h
                uint32_t af[IM][4];
#pragma unroll
                for (int im = 0; im < IM; im++)
                    ldsm4(af[im], st + (a_row + im * 16) * RS + (kp * 2 + h) * 32 + a_half);
#pragma unroll
                for (int im = 0; im < IM; im++)
#pragma unroll
                    for (int jn = 0; jn < JN; jn++)
                        mma1688(acc[im][jn], af[im], &bq[jn][h * 2]);
            }
        }
        buf = (buf + 1 == 3) ? 0 : buf + 1;
    }

    // epilogue
#pragma unroll
    for (int im = 0; im < IM; im++) {
#pragma unroll
        for (int jn = 0; jn < JN; jn++) {
            int r = m0 + wm0 + im * 16 + (lane >> 2);
            int c = n0 + wn0 + jn * 8 + (lane & 3) * 2;
#pragma unroll
            for (int half = 0; half < 2; half++) {
                int rr = r + half * 8;
                float t0 = acc[im][jn][half * 2 + 0];
                float t1 = acc[im][jn][half * 2 + 1];
                if (bias) { t0 += bias[c]; t1 += bias[c + 1]; }
                if (EPI == 1) {
                    t0 = fmaxf(t0, 0.f) + log1pf(expf(-fabsf(t0)));
                    t1 = fmaxf(t1, 0.f) + log1pf(expf(-fabsf(t1)));
                }
                if (RND) { t0 = rtf(t0); t1 = rtf(t1); }
                *(float2*)(C + (size_t)rr * ldc + c) = make_float2(t0, t1);
            }
        }
    }
}

// ---------------- depthwise conv1d, k=4, pad (1,2); div/mod-free -------------
__global__ void __launch_bounds__(256)
conv_k(const float* __restrict__ xr, const float* __restrict__ w,
       const float* __restrict__ cb, float* __restrict__ out)
{
    const int m = blockIdx.x;
    const int t = m & (LSEQ - 1);
    const size_t rowb = (size_t)m * (2 * DINNER);
    const bool hm1 = (t >= 1), hp1 = (t <= LSEQ - 2), hp2 = (t <= LSEQ - 3);

#pragma unroll
    for (int g = 0; g < 2; g++) {
        const int d = (threadIdx.x + g * 256) * 4;
        float4 wv0 = *(const float4*)(w + (size_t)(d + 0) * 4);
        float4 wv1 = *(const float4*)(w + (size_t)(d + 1) * 4);
        float4 wv2 = *(const float4*)(w + (size_t)(d + 2) * 4);
        float4 wv3 = *(const float4*)(w + (size_t)(d + 3) * 4);
        float4 bv = *(const float4*)(cb + d);

        float4 xm1 = hm1 ? *(const float4*)(xr + rowb - 2 * DINNER + d) : make_float4(0,0,0,0);
        float4 x0  = *(const float4*)(xr + rowb + d);
        float4 xp1 = hp1 ? *(const float4*)(xr + rowb + 2 * DINNER + d) : make_float4(0,0,0,0);
        float4 xp2 = hp2 ? *(const float4*)(xr + rowb + 4 * DINNER + d) : make_float4(0,0,0,0);

        float4 o;
        o.x = rtf(bv.x + wv0.x * xm1.x + wv0.y * x0.x + wv0.z * xp1.x + wv0.w * xp2.x);
        o.y = rtf(bv.y + wv1.x * xm1.y + wv1.y * x0.y + wv1.z * xp1.y + wv1.w * xp2.y);
        o.z = rtf(bv.z + wv2.x * xm1.z + wv2.y * x0.z + wv2.z * xp1.z + wv2.w * xp2.z);
        o.w = rtf(bv.w + wv3.x * xm1.w + wv3.y * x0.w + wv3.z * xp1.w + wv3.w * xp2.w);
        *(float4*)(out + (size_t)m * DINNER + d) = o;
    }
}

// ---------------- selective scan + D skip + silu gating ----------------------
#define ST 64
#define SCD 64
__global__ void __launch_bounds__(SCD)
scan_k(const float* __restrict__ xdbl, const float* __restrict__ delta,
       const float* __restrict__ u, const float* __restrict__ xr,
       const float* __restrict__ Alog, const float* __restrict__ Dp,
       float* __restrict__ z)
{
    extern __shared__ float sm[];
    float* sD  = sm;
    float* sU  = sm + 2 * ST * 64;
    float* sR  = sm + 4 * ST * 64;
    float* sBC = sm + 6 * ST * 64;
    const uint32_t sbase = smem_u32(sm);

    const int tid = threadIdx.x;
    const int b = blockIdx.x / (DINNER / SCD);
    const int d0 = (blockIdx.x % (DINNER / SCD)) * SCD;
    const int d = d0 + tid;

    float a[DSTATE];
#pragma unroll
    for (int n = 0; n < DSTATE; n++) a[n] = -__expf(Alog[d * DSTATE + n]);
    bool geo = true;
#pragma unroll
    for (int n = 1; n < DSTATE; n++)
        geo = geo && (fabsf(a[n] - (float)(n + 1) * a[0]) <= 1e-4f * (float)(n + 1) * fabsf(a[0]));

    const float dd = Dp[d];
    float h[DSTATE];
#pragma unroll
    for (int n = 0; n < DSTATE; n++) h[n] = 0.f;

    auto stage = [&](int c, int buf) {
        const int t0 = c * ST;
        for (int i = tid; i < ST * 16; i += SCD) {
            int t = i >> 4, q = i & 15;
            size_t m = (size_t)(b * LSEQ + t0 + t);
            uint32_t so = (uint32_t)((buf * ST * 64 + t * 64 + q * 4) * 4);
            cpa16(sbase + so, delta + m * DINNER + d0 + q * 4);
            cpa16(sbase + 2 * ST * 64 * 4 + so, u + m * DINNER + d0 + q * 4);
            cpa16(sbase + 4 * ST * 64 * 4 + so, xr + m * (2 * DINNER) + DINNER + d0 + q * 4);
        }
        for (int i = tid; i < ST * 8; i += SCD) {
            int t = i >> 3, q = i & 7;
            uint32_t so = (uint32_t)(6 * ST * 64 * 4 + (buf * ST * 32 + t * 32 + q * 4) * 4);
            cpa16(sbase + so, xdbl + (size_t)(b * LSEQ + t0 + t) * XPDIM + DTRANK + q * 4);
        }
        CP_COMMIT();
    };

    const int NCH = LSEQ / ST;
    stage(0, 0);
    for (int c = 0; c < NCH; c++) {
        const int buf = c & 1;
        if (c + 1 < NCH) { stage(c + 1, (c + 1) & 1); CP_WAIT(1); }
        else             { CP_WAIT(0); }
        __syncthreads();

        const float* pD  = sD  + buf * ST * 64;
        const float* pU  = sU  + buf * ST * 64;
        const float* pR  = sR  + buf * ST * 64;
        const float* pBC = sBC + buf * ST * 32;

        for (int tt = 0; tt < ST; tt++) {
            float dlt = pD[tt * 64 + tid];
            float uu  = pU[tt * 64 + tid];
            float rr  = pR[tt * 64 + tid];
            float du = dlt * uu;

            float bv[DSTATE], cv[DSTATE];
#pragma unroll
            for (int q = 0; q < 4; q++) {
                float4 vb = *(const float4*)(pBC + tt * 32 + q * 4);
                bv[q*4+0]=vb.x; bv[q*4+1]=vb.y; bv[q*4+2]=vb.z; bv[q*4+3]=vb.w;
                float4 vc = *(const float4*)(pBC + tt * 32 + 16 + q * 4);
                cv[q*4+0]=vc.x; cv[q*4+1]=vc.y; cv[q*4+2]=vc.z; cv[q*4+3]=vc.w;
            }

            float y0 = 0.f, y1 = 0.f, y2 = 0.f, y3 = 0.f;
            if (geo) {
                float p[DSTATE];
                p[0] = __expf(dlt * a[0]);
#pragma unroll
                for (int n = 1; n < DSTATE; n++) p[n] = p[(n - 1) >> 1] * p[n >> 1];
#pragma unroll
                for (int n = 0; n < DSTATE; n++) {
                    h[n] = p[n] * h[n] + du * bv[n];
                    float t = h[n] * cv[n];
                    if ((n & 3) == 0) y0 += t; else if ((n & 3) == 1) y1 += t;
                    else if ((n & 3) == 2) y2 += t; else y3 += t;
                }
            } else {
#pragma unroll
                for (int n = 0; n < DSTATE; n++) {
                    float dA = __expf(dlt * a[n]);
                    h[n] = dA * h[n] + du * bv[n];
                    float t = h[n] * cv[n];
                    if ((n & 3) == 0) y0 += t; else if ((n & 3) == 1) y1 += t;
                    else if ((n & 3) == 2) y2 += t; else y3 += t;
                }
            }
            float y = (y0 + y1) + (y2 + y3) + uu * dd;

            float sg = 1.f / (1.f + __expf(-rr));
            size_t m = (size_t)(b * LSEQ + c * ST + tt);
            z[m * DINNER + d] = rtf(y * (rr * sg));
        }
        __syncthreads();
    }
}

// ---------------- launch -----------------------------------------------------
extern "C" void kernel_launch(void* const* d_in, const int* in_sizes, int n_in,
                              void* d_out, int out_size)
{
    (void)in_sizes; (void)n_in; (void)out_size;
    const float* x    = (const float*)d_in[0];
    const float* ipw  = (const float*)d_in[1];
    const float* ipb  = (const float*)d_in[2];
    const float* cw   = (const float*)d_in[3];
    const float* cb   = (const float*)d_in[4];
    const float* xpw  = (const float*)d_in[5];
    const float* dpw  = (const float*)d_in[6];
    const float* dpb  = (const float*)d_in[7];
    const float* alog = (const float*)d_in[8];
    const float* dvec = (const float*)d_in[9];
    const float* opw  = (const float*)d_in[10];
    const float* opb  = (const float*)d_in[11];
    float* out = (float*)d_out;

    float *xr, *xc, *xdbl, *dlt, *z, *xt, *ipt, *xpt, *dpt, *opt;
    cudaGetSymbolAddress((void**)&xr,   g_xr);
    cudaGetSymbolAddress((void**)&xc,   g_xc);
    cudaGetSymbolAddress((void**)&xdbl, g_xdbl);
    cudaGetSymbolAddress((void**)&dlt,  g_dlt);
    cudaGetSymbolAddress((void**)&z,    g_z);
    cudaGetSymbolAddress((void**)&xt,   g_xt);
    cudaGetSymbolAddress((void**)&ipt,  g_ipt);
    cudaGetSymbolAddress((void**)&xpt,  g_xpt);
    cudaGetSymbolAddress((void**)&dpt,  g_dpt);
    cudaGetSymbolAddress((void**)&opt,  g_opt);

    constexpr int SM128 = 3 * (128 * 144 + 128 * 144);  // 110592
    constexpr int SM32  = 3 * (128 * 144 + 32 * 144);   // 69120
    constexpr int SMEM_SCAN = (6 * ST * 64 + 2 * ST * 32) * 4; // 114688
    cudaFuncSetAttribute((const void*)gemm_tf<128,128,2,4,0,0>, cudaFuncAttributeMaxDynamicSharedMemorySize, SM128);
    cudaFuncSetAttribute((const void*)gemm_tf<128,128,2,4,1,0>, cudaFuncAttributeMaxDynamicSharedMemorySize, SM128);
    cudaFuncSetAttribute((const void*)gemm_tf<128,32,8,1,0,1>,  cudaFuncAttributeMaxDynamicSharedMemorySize, SM32);
    cudaFuncSetAttribute((const void*)scan_k, cudaFuncAttributeMaxDynamicSharedMemorySize, SMEM_SCAN);

    // all rounds first (indices 0-4) so the ncu capture (-s 5 -c 1) lands on in_proj
    round_k<<<(MTOT*DMODEL/4+255)/256, 256>>>((const float4*)x, (float4*)xt, MTOT*DMODEL/4);
    round_k<<<(2*DINNER*DMODEL/4+255)/256, 256>>>((const float4*)ipw, (float4*)ipt, 2*DINNER*DMODEL/4);
    round_k<<<(XPDIM*DINNER/4+255)/256, 256>>>((const float4*)xpw, (float4*)xpt, XPDIM*DINNER/4);
    round_k<<<(DINNER*DTRANK/4+255)/256, 256>>>((const float4*)dpw, (float4*)dpt, DINNER*DTRANK/4);
    round_k<<<(DMODEL*DINNER/4+255)/256, 256>>>((const float4*)opw, (float4*)opt, DMODEL*DINNER/4);

    // in_proj (launch index 5 -> profiled)
    gemm_tf<128,128,2,4,0,0><<<dim3(2*DINNER/128, MTOT/128), 256, SM128>>>(
        xt, DMODEL, ipt, DMODEL, xr, 2*DINNER, ipb, DMODEL);

    conv_k<<<MTOT, 256>>>(xr, cw, cb, xc);

    // x_proj
    gemm_tf<128,32,8,1,0,1><<<dim3(XPDIM/32, MTOT/128), 256, SM32>>>(
        xc, DINNER, xpt, DINNER, xdbl, XPDIM, nullptr, DINNER);

    // dt_proj + softplus
    gemm_tf<128,128,2,4,1,0><<<dim3(DINNER/128, MTOT/128), 256, SM128>>>(
        xdbl, XPDIM, dpt, DTRANK, dlt, DINNER, dpb, DTRANK);

    scan_k<<<BB*(DINNER/SCD), SCD, SMEM_SCAN>>>(xdbl, dlt, xc, xr, alog, dvec, z);

    // out_proj
    gemm_tf<128,128,2,4,0,0><<<dim3(DMODEL/128, MTOT/128), 256, SM128>>>(
        z, DINNER, opt, DINNER, out, DMODEL, opb, DINNER);
}

// round 11
// speedup vs baseline: 1.0944x; 1.0944x over previous
#include <cuda_runtime.h>
#include <cuda_bf16.h>
#include <cstdint>
#include <math.h>

#define BB 4
#define LSEQ 2048
#define DMODEL 1024
#define DINNER 2048
#define DSTATE 16
#define DTRANK 128
#define XPDIM 160
#define MTOT (BB*LSEQ)      // 8192

// ---------------- scratch ----------------------------------------------------
static __device__ float g_xr  [(size_t)MTOT * 2 * DINNER];
static __device__ float g_xc  [(size_t)MTOT * DINNER];
static __device__ float g_xdbl[(size_t)MTOT * XPDIM];
static __device__ float g_dlt [(size_t)MTOT * DINNER];
static __device__ float g_z   [(size_t)MTOT * DINNER];
static __device__ float g_xt  [(size_t)MTOT * DMODEL];
static __device__ float g_ipt [(size_t)2*DINNER * DMODEL];
static __device__ float g_xpt [(size_t)XPDIM * DINNER];
static __device__ float g_dpt [(size_t)DINNER * DTRANK];
static __device__ float g_opt [(size_t)DMODEL * DINNER];

// ---------------- PTX helpers ------------------------------------------------
__device__ __forceinline__ uint32_t smem_u32(const void* p) {
    uint32_t a;
    asm("{ .reg .u64 t; cvta.to.shared.u64 t, %1; cvt.u32.u64 %0, t; }" : "=r"(a) : "l"(p));
    return a;
}
__device__ __forceinline__ void cpa16(uint32_t s, const void* g) {
    asm volatile("cp.async.cg.shared.global [%0], [%1], 16;" :: "r"(s), "l"(g));
}
#define CP_COMMIT() asm volatile("cp.async.commit_group;" ::: "memory")
#define CP_WAIT(n)  asm volatile("cp.async.wait_group %0;" :: "n"(n) : "memory")

__device__ __forceinline__ void ldsm4(uint32_t* r, uint32_t a) {
    asm volatile("ldmatrix.sync.aligned.m8n8.x4.shared.b16 {%0,%1,%2,%3}, [%4];"
                 : "=r"(r[0]), "=r"(r[1]), "=r"(r[2]), "=r"(r[3]) : "r"(a));
}
__device__ __forceinline__ void ldsm2(uint32_t* r, uint32_t a) {
    asm volatile("ldmatrix.sync.aligned.m8n8.x2.shared.b16 {%0,%1}, [%2];"
                 : "=r"(r[0]), "=r"(r[1]) : "r"(a));
}
__device__ __forceinline__ void mma1688(float* d, const uint32_t* a, const uint32_t* b) {
    asm volatile(
        "mma.sync.aligned.m16n8k8.row.col.f32.tf32.tf32.f32 "
        "{%0,%1,%2,%3}, {%4,%5,%6,%7}, {%8,%9}, {%0,%1,%2,%3};"
        : "+f"(d[0]), "+f"(d[1]), "+f"(d[2]), "+f"(d[3])
        : "r"(a[0]), "r"(a[1]), "r"(a[2]), "r"(a[3]), "r"(b[0]), "r"(b[1]));
}
__device__ __forceinline__ float rtf(float v) {
    uint32_t r;
    asm("cvt.rna.tf32.f32 %0, %1;" : "=r"(r) : "f"(v));
    return __uint_as_float(r);
}

// vectorized tf32 rounding pass
__global__ void round_k(const float4* __restrict__ in, float4* __restrict__ out, int n4) {
    int i = blockIdx.x * blockDim.x + threadIdx.x;
    if (i < n4) {
        float4 v = in[i];
        v.x = rtf(v.x); v.y = rtf(v.y); v.z = rtf(v.z); v.w = rtf(v.w);
        out[i] = v;
    }
}

// ---------------- tf32 HMMA GEMM: BK=32, 3-stage ring (R9-proven mainloop) ---
template<int BM, int BN, int WARPS_M, int WARPS_N, int EPI, int RND>
__global__ void __launch_bounds__(WARPS_M * WARPS_N * 32)
gemm_tf(const float* __restrict__ A, int lda,
        const float* __restrict__ B, int ldb,
        float* __restrict__ C, int ldc, const float* __restrict__ bias, int K)
{
    constexpr int NT = WARPS_M * WARPS_N * 32;
    constexpr int RS = 144;                 // 32 floats (128B) + 16B pad
    constexpr int SA = BM * RS;
    constexpr int SB = BN * RS;
    constexpr int STAGE = SA + SB;
    constexpr int WM = BM / WARPS_M, WN = BN / WARPS_N;
    constexpr int IM = WM / 16, JN = WN / 8;

    extern __shared__ char smem[];
    const uint32_t sbase = smem_u32(smem);
    const int tid = threadIdx.x;
    const int warp = tid >> 5, lane = tid & 31;
    const int wm0 = (warp / WARPS_N) * WM;
    const int wn0 = (warp % WARPS_N) * WN;
    const int m0 = blockIdx.y * BM, n0 = blockIdx.x * BN;
    const int NC = K >> 5;

    float acc[IM][JN][4];
#pragma unroll
    for (int i = 0; i < IM; i++)
#pragma unroll
        for (int j = 0; j < JN; j++)
#pragma unroll
            for (int q = 0; q < 4; q++) acc[i][j][q] = 0.f;

    auto load_chunk = [&](int kc, int buf) {
        const int k0 = kc << 5;
        const uint32_t st = sbase + buf * STAGE;
        for (int idx = tid; idx < BM * 8; idx += NT) {
            int r = idx >> 3, c = idx & 7;
            cpa16(st + (uint32_t)(r * RS + c * 16), A + (size_t)(m0 + r) * lda + k0 + c * 4);
        }
        for (int idx = tid; idx < BN * 8; idx += NT) {
            int r = idx >> 3, c = idx & 7;
            cpa16(st + SA + (uint32_t)(r * RS + c * 16), B + (size_t)(n0 + r) * ldb + k0 + c * 4);
        }
        CP_COMMIT();
    };

    const uint32_t a_row  = (uint32_t)(wm0 + (lane & 15));
    const uint32_t a_half = (uint32_t)((lane >> 4) * 16);
    const uint32_t b_row  = (uint32_t)(wn0 + (lane & 7));
    const uint32_t b_half = (uint32_t)(((lane >> 3) & 1) * 16);

    // 3-stage ring
    load_chunk(0, 0);
    if (NC > 1) load_chunk(1, 1);

    int buf = 0;
    for (int i = 0; i < NC; i++) {
        if (i + 1 < NC) CP_WAIT(1); else CP_WAIT(0);
        __syncthreads();
        if (i + 2 < NC) load_chunk(i + 2, (buf + 2 >= 3) ? buf - 1 : buf + 2);

        const uint32_t st = sbase + buf * STAGE;
#pragma unroll
        for (int ks = 0; ks < 4; ks++) {
            uint32_t af[IM][4], bf[JN][2];
#pragma unroll
            for (int im = 0; im < IM; im++)
                ldsm4(af[im], st + (a_row + im * 16) * RS + ks * 32 + a_half);
#pragma unroll
            for (int jn = 0; jn < JN; jn++)
                ldsm2(bf[jn], st + SA + (b_row + jn * 8) * RS + ks * 32 + b_half);
#pragma unroll
            for (int im = 0; im < IM; im++)
#pragma unroll
                for (int jn = 0; jn < JN; jn++)
                    mma1688(acc[im][jn], af[im], bf[jn]);
        }
        buf = (buf + 1 == 3) ? 0 : buf + 1;
    }

    // epilogue
#pragma unroll
    for (int im = 0; im < IM; im++) {
#pragma unroll
        for (int jn = 0; jn < JN; jn++) {
            int r = m0 + wm0 + im * 16 + (lane >> 2);
            int c = n0 + wn0 + jn * 8 + (lane & 3) * 2;
#pragma unroll
            for (int half = 0; half < 2; half++) {
                int rr = r + half * 8;
                float t0 = acc[im][jn][half * 2 + 0];
                float t1 = acc[im][jn][half * 2 + 1];
                if (bias) { t0 += bias[c]; t1 += bias[c + 1]; }
                if (EPI == 1) {
                    t0 = fmaxf(t0, 0.f) + log1pf(expf(-fabsf(t0)));
                    t1 = fmaxf(t1, 0.f) + log1pf(expf(-fabsf(t1)));
                }
                if (RND) { t0 = rtf(t0); t1 = rtf(t1); }
                *(float2*)(C + (size_t)rr * ldc + c) = make_float2(t0, t1);
            }
        }
    }
}

// ---------------- depthwise conv1d, k=4, pad (1,2); div/mod-free -------------
__global__ void __launch_bounds__(256)
conv_k(const float* __restrict__ xr, const float* __restrict__ w,
       const float* __restrict__ cb, float* __restrict__ out)
{
    const int m = blockIdx.x;
    const int t = m & (LSEQ - 1);
    const size_t rowb = (size_t)m * (2 * DINNER);
    const bool hm1 = (t >= 1), hp1 = (t <= LSEQ - 2), hp2 = (t <= LSEQ - 3);

#pragma unroll
    for (int g = 0; g < 2; g++) {
        const int d = (threadIdx.x + g * 256) * 4;
        float4 wv0 = *(const float4*)(w + (size_t)(d + 0) * 4);
        float4 wv1 = *(const float4*)(w + (size_t)(d + 1) * 4);
        float4 wv2 = *(const float4*)(w + (size_t)(d + 2) * 4);
        float4 wv3 = *(const float4*)(w + (size_t)(d + 3) * 4);
        float4 bv = *(const float4*)(cb + d);

        float4 xm1 = hm1 ? *(const float4*)(xr + rowb - 2 * DINNER + d) : make_float4(0,0,0,0);
        float4 x0  = *(const float4*)(xr + rowb + d);
        float4 xp1 = hp1 ? *(const float4*)(xr + rowb + 2 * DINNER + d) : make_float4(0,0,0,0);
        float4 xp2 = hp2 ? *(const float4*)(xr + rowb + 4 * DINNER + d) : make_float4(0,0,0,0);

        float4 o;
        o.x = rtf(bv.x + wv0.x * xm1.x + wv0.y * x0.x + wv0.z * xp1.x + wv0.w * xp2.x);
        o.y = rtf(bv.y + wv1.x * xm1.y + wv1.y * x0.y + wv1.z * xp1.y + wv1.w * xp2.y);
        o.z = rtf(bv.z + wv2.x * xm1.z + wv2.y * x0.z + wv2.z * xp1.z + wv2.w * xp2.z);
        o.w = rtf(bv.w + wv3.x * xm1.w + wv3.y * x0.w + wv3.z * xp1.w + wv3.w * xp2.w);
        *(float4*)(out + (size_t)m * DINNER + d) = o;
    }
}

// ---------------- selective scan + D skip + silu gating ----------------------
#define ST 64
#define SCD 64
__global__ void __launch_bounds__(SCD)
scan_k(const float* __restrict__ xdbl, const float* __restrict__ delta,
       const float* __restrict__ u, const float* __restrict__ xr,
       const float* __restrict__ Alog, const float* __restrict__ Dp,
       float* __restrict__ z)
{
    extern __shared__ float sm[];
    float* sD  = sm;
    float* sU  = sm + 2 * ST * 64;
    float* sR  = sm + 4 * ST * 64;
    float* sBC = sm + 6 * ST * 64;
    const uint32_t sbase = smem_u32(sm);

    const int tid = threadIdx.x;
    const int b = blockIdx.x / (DINNER / SCD);
    const int d0 = (blockIdx.x % (DINNER / SCD)) * SCD;
    const int d = d0 + tid;

    float a[DSTATE];
#pragma unroll
    for (int n = 0; n < DSTATE; n++) a[n] = -__expf(Alog[d * DSTATE + n]);
    bool geo = true;
#pragma unroll
    for (int n = 1; n < DSTATE; n++)
        geo = geo && (fabsf(a[n] - (float)(n + 1) * a[0]) <= 1e-4f * (float)(n + 1) * fabsf(a[0]));

    const float dd = Dp[d];
    float h[DSTATE];
#pragma unroll
    for (int n = 0; n < DSTATE; n++) h[n] = 0.f;

    auto stage = [&](int c, int buf) {
        const int t0 = c * ST;
        for (int i = tid; i < ST * 16; i += SCD) {
            int t = i >> 4, q = i & 15;
            size_t m = (size_t)(b * LSEQ + t0 + t);
            uint32_t so = (uint32_t)((buf * ST * 64 + t * 64 + q * 4) * 4);
            cpa16(sbase + so, delta + m * DINNER + d0 + q * 4);
            cpa16(sbase + 2 * ST * 64 * 4 + so, u + m * DINNER + d0 + q * 4);
            cpa16(sbase + 4 * ST * 64 * 4 + so, xr + m * (2 * DINNER) + DINNER + d0 + q * 4);
        }
        for (int i = tid; i < ST * 8; i += SCD) {
            int t = i >> 3, q = i & 7;
            uint32_t so = (uint32_t)(6 * ST * 64 * 4 + (buf * ST * 32 + t * 32 + q * 4) * 4);
            cpa16(sbase + so, xdbl + (size_t)(b * LSEQ + t0 + t) * XPDIM + DTRANK + q * 4);
        }
        CP_COMMIT();
    };

    const int NCH = LSEQ / ST;
    stage(0, 0);
    for (int c = 0; c < NCH; c++) {
        const int buf = c & 1;
        if (c + 1 < NCH) { stage(c + 1, (c + 1) & 1); CP_WAIT(1); }
        else             { CP_WAIT(0); }
        __syncthreads();

        const float* pD  = sD  + buf * ST * 64;
        const float* pU  = sU  + buf * ST * 64;
        const float* pR  = sR  + buf * ST * 64;
        const float* pBC = sBC + buf * ST * 32;

        for (int tt = 0; tt < ST; tt++) {
            float dlt = pD[tt * 64 + tid];
            float uu  = pU[tt * 64 + tid];
            float rr  = pR[tt * 64 + tid];
            float du = dlt * uu;

            float bv[DSTATE], cv[DSTATE];
#pragma unroll
            for (int q = 0; q < 4; q++) {
                float4 vb = *(const float4*)(pBC + tt * 32 + q * 4);
                bv[q*4+0]=vb.x; bv[q*4+1]=vb.y; bv[q*4+2]=vb.z; bv[q*4+3]=vb.w;
                float4 vc = *(const float4*)(pBC + tt * 32 + 16 + q * 4);
                cv[q*4+0]=vc.x; cv[q*4+1]=vc.y; cv[q*4+2]=vc.z; cv[q*4+3]=vc.w;
            }

            float y0 = 0.f, y1 = 0.f, y2 = 0.f, y3 = 0.f;
            if (geo) {
                float p[DSTATE];
                p[0] = __expf(dlt * a[0]);
#pragma unroll
                for (int n = 1; n < DSTATE; n++) p[n] = p[(n - 1) >> 1] * p[n >> 1];
#pragma unroll
                for (int n = 0; n < DSTATE; n++) {
                    h[n] = p[n] * h[n] + du * bv[n];
                    float t = h[n] * cv[n];
                    if ((n & 3) == 0) y0 += t; else if ((n & 3) == 1) y1 += t;
                    else if ((n & 3) == 2) y2 += t; else y3 += t;
                }
            } else {
#pragma unroll
                for (int n = 0; n < DSTATE; n++) {
                    float dA = __expf(dlt * a[n]);
                    h[n] = dA * h[n] + du * bv[n];
                    float t = h[n] * cv[n];
                    if ((n & 3) == 0) y0 += t; else if ((n & 3) == 1) y1 += t;
                    else if ((n & 3) == 2) y2 += t; else y3 += t;
                }
            }
            float y = (y0 + y1) + (y2 + y3) + uu * dd;

            float sg = 1.f / (1.f + __expf(-rr));
            size_t m = (size_t)(b * LSEQ + c * ST + tt);
            z[m * DINNER + d] = rtf(y * (rr * sg));
        }
        __syncthreads();
    }
}

// ---------------- launch -----------------------------------------------------
extern "C" void kernel_launch(void* const* d_in, const int* in_sizes, int n_in,
                              void* d_out, int out_size)
{
    (void)in_sizes; (void)n_in; (void)out_size;
    const float* x    = (const float*)d_in[0];
    const float* ipw  = (const float*)d_in[1];
    const float* ipb  = (const float*)d_in[2];
    const float* cw   = (const float*)d_in[3];
    const float* cb   = (const float*)d_in[4];
    const float* xpw  = (const float*)d_in[5];
    const float* dpw  = (const float*)d_in[6];
    const float* dpb  = (const float*)d_in[7];
    const float* alog = (const float*)d_in[8];
    const float* dvec = (const float*)d_in[9];
    const float* opw  = (const float*)d_in[10];
    const float* opb  = (const float*)d_in[11];
    float* out = (float*)d_out;

    float *xr, *xc, *xdbl, *dlt, *z, *xt, *ipt, *xpt, *dpt, *opt;
    cudaGetSymbolAddress((void**)&xr,   g_xr);
    cudaGetSymbolAddress((void**)&xc,   g_xc);
    cudaGetSymbolAddress((void**)&xdbl, g_xdbl);
    cudaGetSymbolAddress((void**)&dlt,  g_dlt);
    cudaGetSymbolAddress((void**)&z,    g_z);
    cudaGetSymbolAddress((void**)&xt,   g_xt);
    cudaGetSymbolAddress((void**)&ipt,  g_ipt);
    cudaGetSymbolAddress((void**)&xpt,  g_xpt);
    cudaGetSymbolAddress((void**)&dpt,  g_dpt);
    cudaGetSymbolAddress((void**)&opt,  g_opt);

    constexpr int SM128 = 3 * (128 * 144 + 128 * 144);  // 110592
    constexpr int SM256 = 3 * (128 * 144 + 256 * 144);  // 165888 (in_proj wide)
    constexpr int SM32  = 3 * (128 * 144 + 32 * 144);   // 69120
    constexpr int SMEM_SCAN = (6 * ST * 64 + 2 * ST * 32) * 4; // 114688
    cudaFuncSetAttribute((const void*)gemm_tf<128,256,2,8,0,0>, cudaFuncAttributeMaxDynamicSharedMemorySize, SM256);
    cudaFuncSetAttribute((const void*)gemm_tf<128,128,2,4,0,0>, cudaFuncAttributeMaxDynamicSharedMemorySize, SM128);
    cudaFuncSetAttribute((const void*)gemm_tf<128,128,2,4,1,0>, cudaFuncAttributeMaxDynamicSharedMemorySize, SM128);
    cudaFuncSetAttribute((const void*)gemm_tf<128,32,8,1,0,1>,  cudaFuncAttributeMaxDynamicSharedMemorySize, SM32);
    cudaFuncSetAttribute((const void*)scan_k, cudaFuncAttributeMaxDynamicSharedMemorySize, SMEM_SCAN);

    // launch order: in_proj at index 3 (the ncu capture consistently profiles index 3)
    round_k<<<(MTOT*DMODEL/4+255)/256, 256>>>((const float4*)x, (float4*)xt, MTOT*DMODEL/4);        // 0
    round_k<<<(2*DINNER*DMODEL/4+255)/256, 256>>>((const float4*)ipw, (float4*)ipt, 2*DINNER*DMODEL/4); // 1
    round_k<<<(XPDIM*DINNER/4+255)/256, 256>>>((const float4*)xpw, (float4*)xpt, XPDIM*DINNER/4);   // 2

    // in_proj (PROFILED): wide 128x256 tiles, 512 threads, -25% L2 traffic     // 3
    gemm_tf<128,256,2,8,0,0><<<dim3(2*DINNER/256, MTOT/128), 512, SM256>>>(
        xt, DMODEL, ipt, DMODEL, xr, 2*DINNER, ipb, DMODEL);

    conv_k<<<MTOT, 256>>>(xr, cw, cb, xc);                                      // 4
    round_k<<<(DINNER*DTRANK/4+255)/256, 256>>>((const float4*)dpw, (float4*)dpt, DINNER*DTRANK/4); // 5

    // x_proj                                                                   // 6
    gemm_tf<128,32,8,1,0,1><<<dim3(XPDIM/32, MTOT/128), 256, SM32>>>(
        xc, DINNER, xpt, DINNER, xdbl, XPDIM, nullptr, DINNER);

    // dt_proj + softplus                                                       // 7
    gemm_tf<128,128,2,4,1,0><<<dim3(DINNER/128, MTOT/128), 256, SM128>>>(
        xdbl, XPDIM, dpt, DTRANK, dlt, DINNER, dpb, DTRANK);

    round_k<<<(DMODEL*DINNER/4+255)/256, 256>>>((const float4*)opw, (float4*)opt, DMODEL*DINNER/4); // 8
    scan_k<<<BB*(DINNER/SCD), SCD, SMEM_SCAN>>>(xdbl, dlt, xc, xr, alog, dvec, z);                  // 9

    // out_proj                                                                 // 10
    gemm_tf<128,128,2,4,0,0><<<dim3(DMODEL/128, MTOT/128), 256, SM128>>>(
        z, DINNER, opt, DINNER, out, DMODEL, opb, DINNER);
}

// round 12
// speedup vs baseline: 1.1342x; 1.0364x over previous
#include <cuda_runtime.h>
#include <cuda_bf16.h>
#include <cstdint>
#include <math.h>

#define BB 4
#define LSEQ 2048
#define DMODEL 1024
#define DINNER 2048
#define DSTATE 16
#define DTRANK 128
#define XPDIM 160
#define MTOT (BB*LSEQ)      // 8192

// ---------------- scratch ----------------------------------------------------
static __device__ float g_xr  [(size_t)MTOT * 2 * DINNER];
static __device__ float g_xc  [(size_t)MTOT * DINNER];
static __device__ float g_xdbl[(size_t)MTOT * XPDIM];
static __device__ float g_dlt [(size_t)MTOT * DINNER];
static __device__ float g_z   [(size_t)MTOT * DINNER];
static __device__ float g_xt  [(size_t)MTOT * DMODEL];
static __device__ float g_ipt [(size_t)2*DINNER * DMODEL];
static __device__ float g_xpt [(size_t)XPDIM * DINNER];
static __device__ float g_dpt [(size_t)DINNER * DTRANK];
static __device__ float g_opt [(size_t)DMODEL * DINNER];

// ---------------- PTX helpers ------------------------------------------------
__device__ __forceinline__ uint32_t smem_u32(const void* p) {
    uint32_t a;
    asm("{ .reg .u64 t; cvta.to.shared.u64 t, %1; cvt.u32.u64 %0, t; }" : "=r"(a) : "l"(p));
    return a;
}
__device__ __forceinline__ void cpa16(uint32_t s, const void* g) {
    asm volatile("cp.async.cg.shared.global [%0], [%1], 16;" :: "r"(s), "l"(g));
}
#define CP_COMMIT() asm volatile("cp.async.commit_group;" ::: "memory")
#define CP_WAIT(n)  asm volatile("cp.async.wait_group %0;" :: "n"(n) : "memory")

__device__ __forceinline__ void ldsm4(uint32_t* r, uint32_t a) {
    asm volatile("ldmatrix.sync.aligned.m8n8.x4.shared.b16 {%0,%1,%2,%3}, [%4];"
                 : "=r"(r[0]), "=r"(r[1]), "=r"(r[2]), "=r"(r[3]) : "r"(a));
}
__device__ __forceinline__ void ldsm2(uint32_t* r, uint32_t a) {
    asm volatile("ldmatrix.sync.aligned.m8n8.x2.shared.b16 {%0,%1}, [%2];"
                 : "=r"(r[0]), "=r"(r[1]) : "r"(a));
}
__device__ __forceinline__ void mma1688(float* d, const uint32_t* a, const uint32_t* b) {
    asm volatile(
        "mma.sync.aligned.m16n8k8.row.col.f32.tf32.tf32.f32 "
        "{%0,%1,%2,%3}, {%4,%5,%6,%7}, {%8,%9}, {%0,%1,%2,%3};"
        : "+f"(d[0]), "+f"(d[1]), "+f"(d[2]), "+f"(d[3])
        : "r"(a[0]), "r"(a[1]), "r"(a[2]), "r"(a[3]), "r"(b[0]), "r"(b[1]));
}
__device__ __forceinline__ float rtf(float v) {
    uint32_t r;
    asm("cvt.rna.tf32.f32 %0, %1;" : "=r"(r) : "f"(v));
    return __uint_as_float(r);
}

// vectorized tf32 rounding pass
__global__ void round_k(const float4* __restrict__ in, float4* __restrict__ out, int n4) {
    int i = blockIdx.x * blockDim.x + threadIdx.x;
    if (i < n4) {
        float4 v = in[i];
        v.x = rtf(v.x); v.y = rtf(v.y); v.z = rtf(v.z); v.w = rtf(v.w);
        out[i] = v;
    }
}

// ---------------- tf32 HMMA GEMM: BK=32, 3-stage ring, frag double-buffer ----
// 1 block/SM at this smem size -> register headroom is free; af/bf for ks+1
// are loaded before the mmas of ks to hide LDSM latency under tensor work.
template<int BM, int BN, int WARPS_M, int WARPS_N, int EPI, int RND>
__global__ void __launch_bounds__(WARPS_M * WARPS_N * 32)
gemm_tf(const float* __restrict__ A, int lda,
        const float* __restrict__ B, int ldb,
        float* __restrict__ C, int ldc, const float* __restrict__ bias, int K)
{
    constexpr int NT = WARPS_M * WARPS_N * 32;
    constexpr int RS = 144;                 // 32 floats (128B) + 16B pad
    constexpr int SA = BM * RS;
    constexpr int SB = BN * RS;
    constexpr int STAGE = SA + SB;
    constexpr int WM = BM / WARPS_M, WN = BN / WARPS_N;
    constexpr int IM = WM / 16, JN = WN / 8;

    extern __shared__ char smem[];
    const uint32_t sbase = smem_u32(smem);
    const int tid = threadIdx.x;
    const int warp = tid >> 5, lane = tid & 31;
    const int wm0 = (warp / WARPS_N) * WM;
    const int wn0 = (warp % WARPS_N) * WN;
    const int m0 = blockIdx.y * BM, n0 = blockIdx.x * BN;
    const int NC = K >> 5;

    float acc[IM][JN][4];
#pragma unroll
    for (int i = 0; i < IM; i++)
#pragma unroll
        for (int j = 0; j < JN; j++)
#pragma unroll
            for (int q = 0; q < 4; q++) acc[i][j][q] = 0.f;

    auto load_chunk = [&](int kc, int buf) {
        const int k0 = kc << 5;
        const uint32_t st = sbase + buf * STAGE;
        for (int idx = tid; idx < BM * 8; idx += NT) {
            int r = idx >> 3, c = idx & 7;
            cpa16(st + (uint32_t)(r * RS + c * 16), A + (size_t)(m0 + r) * lda + k0 + c * 4);
        }
        for (int idx = tid; idx < BN * 8; idx += NT) {
            int r = idx >> 3, c = idx & 7;
            cpa16(st + SA + (uint32_t)(r * RS + c * 16), B + (size_t)(n0 + r) * ldb + k0 + c * 4);
        }
        CP_COMMIT();
    };

    const uint32_t a_row  = (uint32_t)(wm0 + (lane & 15));
    const uint32_t a_half = (uint32_t)((lane >> 4) * 16);
    const uint32_t b_row  = (uint32_t)(wn0 + (lane & 7));
    const uint32_t b_half = (uint32_t)(((lane >> 3) & 1) * 16);

    // 3-stage ring
    load_chunk(0, 0);
    if (NC > 1) load_chunk(1, 1);

    int buf = 0;
    for (int i = 0; i < NC; i++) {
        if (i + 1 < NC) CP_WAIT(1); else CP_WAIT(0);
        __syncthreads();
        if (i + 2 < NC) load_chunk(i + 2, (buf + 2 >= 3) ? buf - 1 : buf + 2);

        const uint32_t st = sbase + buf * STAGE;
        uint32_t af[2][IM][4], bf[2][JN][2];

        auto ldfrag = [&](int ks, int p) {
#pragma unroll
            for (int im = 0; im < IM; im++)
                ldsm4(af[p][im], st + (a_row + im * 16) * RS + ks * 32 + a_half);
#pragma unroll
            for (int jn = 0; jn < JN; jn++)
                ldsm2(bf[p][jn], st + SA + (b_row + jn * 8) * RS + ks * 32 + b_half);
        };

        ldfrag(0, 0);
#pragma unroll
        for (int ks = 0; ks < 4; ks++) {
            const int cur = ks & 1;
            if (ks < 3) ldfrag(ks + 1, cur ^ 1);
#pragma unroll
            for (int im = 0; im < IM; im++)
#pragma unroll
                for (int jn = 0; jn < JN; jn++)
                    mma1688(acc[im][jn], af[cur][im], bf[cur][jn]);
        }
        buf = (buf + 1 == 3) ? 0 : buf + 1;
    }

    // epilogue
#pragma unroll
    for (int im = 0; im < IM; im++) {
#pragma unroll
        for (int jn = 0; jn < JN; jn++) {
            int r = m0 + wm0 + im * 16 + (lane >> 2);
            int c = n0 + wn0 + jn * 8 + (lane & 3) * 2;
#pragma unroll
            for (int half = 0; half < 2; half++) {
                int rr = r + half * 8;
                float t0 = acc[im][jn][half * 2 + 0];
                float t1 = acc[im][jn][half * 2 + 1];
                if (bias) { t0 += bias[c]; t1 += bias[c + 1]; }
                if (EPI == 1) {
                    t0 = fmaxf(t0, 0.f) + log1pf(expf(-fabsf(t0)));
                    t1 = fmaxf(t1, 0.f) + log1pf(expf(-fabsf(t1)));
                }
                if (RND) { t0 = rtf(t0); t1 = rtf(t1); }
                *(float2*)(C + (size_t)rr * ldc + c) = make_float2(t0, t1);
            }
        }
    }
}

// ---------------- depthwise conv1d, k=4, pad (1,2); div/mod-free -------------
__global__ void __launch_bounds__(256)
conv_k(const float* __restrict__ xr, const float* __restrict__ w,
       const float* __restrict__ cb, float* __restrict__ out)
{
    const int m = blockIdx.x;
    const int t = m & (LSEQ - 1);
    const size_t rowb = (size_t)m * (2 * DINNER);
    const bool hm1 = (t >= 1), hp1 = (t <= LSEQ - 2), hp2 = (t <= LSEQ - 3);

#pragma unroll
    for (int g = 0; g < 2; g++) {
        const int d = (threadIdx.x + g * 256) * 4;
        float4 wv0 = *(const float4*)(w + (size_t)(d + 0) * 4);
        float4 wv1 = *(const float4*)(w + (size_t)(d + 1) * 4);
        float4 wv2 = *(const float4*)(w + (size_t)(d + 2) * 4);
        float4 wv3 = *(const float4*)(w + (size_t)(d + 3) * 4);
        float4 bv = *(const float4*)(cb + d);

        float4 xm1 = hm1 ? *(const float4*)(xr + rowb - 2 * DINNER + d) : make_float4(0,0,0,0);
        float4 x0  = *(const float4*)(xr + rowb + d);
        float4 xp1 = hp1 ? *(const float4*)(xr + rowb + 2 * DINNER + d) : make_float4(0,0,0,0);
        float4 xp2 = hp2 ? *(const float4*)(xr + rowb + 4 * DINNER + d) : make_float4(0,0,0,0);

        float4 o;
        o.x = rtf(bv.x + wv0.x * xm1.x + wv0.y * x0.x + wv0.z * xp1.x + wv0.w * xp2.x);
        o.y = rtf(bv.y + wv1.x * xm1.y + wv1.y * x0.y + wv1.z * xp1.y + wv1.w * xp2.y);
        o.z = rtf(bv.z + wv2.x * xm1.z + wv2.y * x0.z + wv2.z * xp1.z + wv2.w * xp2.z);
        o.w = rtf(bv.w + wv3.x * xm1.w + wv3.y * x0.w + wv3.z * xp1.w + wv3.w * xp2.w);
        *(float4*)(out + (size_t)m * DINNER + d) = o;
    }
}

// ---------------- selective scan + D skip + silu gating ----------------------
#define ST 64
#define SCD 64
__global__ void __launch_bounds__(SCD)
scan_k(const float* __restrict__ xdbl, const float* __restrict__ delta,
       const float* __restrict__ u, const float* __restrict__ xr,
       const float* __restrict__ Alog, const float* __restrict__ Dp,
       float* __restrict__ z)
{
    extern __shared__ float sm[];
    float* sD  = sm;
    float* sU  = sm + 2 * ST * 64;
    float* sR  = sm + 4 * ST * 64;
    float* sBC = sm + 6 * ST * 64;
    const uint32_t sbase = smem_u32(sm);

    const int tid = threadIdx.x;
    const int b = blockIdx.x / (DINNER / SCD);
    const int d0 = (blockIdx.x % (DINNER / SCD)) * SCD;
    const int d = d0 + tid;

    float a[DSTATE];
#pragma unroll
    for (int n = 0; n < DSTATE; n++) a[n] = -__expf(Alog[d * DSTATE + n]);
    bool geo = true;
#pragma unroll
    for (int n = 1; n < DSTATE; n++)
        geo = geo && (fabsf(a[n] - (float)(n + 1) * a[0]) <= 1e-4f * (float)(n + 1) * fabsf(a[0]));

    const float dd = Dp[d];
    float h[DSTATE];
#pragma unroll
    for (int n = 0; n < DSTATE; n++) h[n] = 0.f;

    auto stage = [&](int c, int buf) {
        const int t0 = c * ST;
        for (int i = tid; i < ST * 16; i += SCD) {
            int t = i >> 4, q = i & 15;
            size_t m = (size_t)(b * LSEQ + t0 + t);
            uint32_t so = (uint32_t)((buf * ST * 64 + t * 64 + q * 4) * 4);
            cpa16(sbase + so, delta + m * DINNER + d0 + q * 4);
            cpa16(sbase + 2 * ST * 64 * 4 + so, u + m * DINNER + d0 + q * 4);
            cpa16(sbase + 4 * ST * 64 * 4 + so, xr + m * (2 * DINNER) + DINNER + d0 + q * 4);
        }
        for (int i = tid; i < ST * 8; i += SCD) {
            int t = i >> 3, q = i & 7;
            uint32_t so = (uint32_t)(6 * ST * 64 * 4 + (buf * ST * 32 + t * 32 + q * 4) * 4);
            cpa16(sbase + so, xdbl + (size_t)(b * LSEQ + t0 + t) * XPDIM + DTRANK + q * 4);
        }
        CP_COMMIT();
    };

    const int NCH = LSEQ / ST;
    stage(0, 0);
    for (int c = 0; c < NCH; c++) {
        const int buf = c & 1;
        if (c + 1 < NCH) { stage(c + 1, (c + 1) & 1); CP_WAIT(1); }
        else             { CP_WAIT(0); }
        __syncthreads();

        const float* pD  = sD  + buf * ST * 64;
        const float* pU  = sU  + buf * ST * 64;
        const float* pR  = sR  + buf * ST * 64;
        const float* pBC = sBC + buf * ST * 32;

        for (int tt = 0; tt < ST; tt++) {
            float dlt = pD[tt * 64 + tid];
            float uu  = pU[tt * 64 + tid];
            float rr  = pR[tt * 64 + tid];
            float du = dlt * uu;

            float bv[DSTATE], cv[DSTATE];
#pragma unroll
            for (int q = 0; q < 4; q++) {
                float4 vb = *(const float4*)(pBC + tt * 32 + q * 4);
                bv[q*4+0]=vb.x; bv[q*4+1]=vb.y; bv[q*4+2]=vb.z; bv[q*4+3]=vb.w;
                float4 vc = *(const float4*)(pBC + tt * 32 + 16 + q * 4);
                cv[q*4+0]=vc.x; cv[q*4+1]=vc.y; cv[q*4+2]=vc.z; cv[q*4+3]=vc.w;
            }

            float y0 = 0.f, y1 = 0.f, y2 = 0.f, y3 = 0.f;
            if (geo) {
                float p[DSTATE];
                p[0] = __expf(dlt * a[0]);
#pragma unroll
                for (int n = 1; n < DSTATE; n++) p[n] = p[(n - 1) >> 1] * p[n >> 1];
#pragma unroll
                for (int n = 0; n < DSTATE; n++) {
                    h[n] = p[n] * h[n] + du * bv[n];
                    float t = h[n] * cv[n];
                    if ((n & 3) == 0) y0 += t; else if ((n & 3) == 1) y1 += t;
                    else if ((n & 3) == 2) y2 += t; else y3 += t;
                }
            } else {
#pragma unroll
                for (int n = 0; n < DSTATE; n++) {
                    float dA = __expf(dlt * a[n]);
                    h[n] = dA * h[n] + du * bv[n];
                    float t = h[n] * cv[n];
                    if ((n & 3) == 0) y0 += t; else if ((n & 3) == 1) y1 += t;
                    else if ((n & 3) == 2) y2 += t; else y3 += t;
                }
            }
            float y = (y0 + y1) + (y2 + y3) + uu * dd;

            float sg = 1.f / (1.f + __expf(-rr));
            size_t m = (size_t)(b * LSEQ + c * ST + tt);
            z[m * DINNER + d] = rtf(y * (rr * sg));
        }
        __syncthreads();
    }
}

// ---------------- launch -----------------------------------------------------
extern "C" void kernel_launch(void* const* d_in, const int* in_sizes, int n_in,
                              void* d_out, int out_size)
{
    (void)in_sizes; (void)n_in; (void)out_size;
    const float* x    = (const float*)d_in[0];
    const float* ipw  = (const float*)d_in[1];
    const float* ipb  = (const float*)d_in[2];
    const float* cw   = (const float*)d_in[3];
    const float* cb   = (const float*)d_in[4];
    const float* xpw  = (const float*)d_in[5];
    const float* dpw  = (const float*)d_in[6];
    const float* dpb  = (const float*)d_in[7];
    const float* alog = (const float*)d_in[8];
    const float* dvec = (const float*)d_in[9];
    const float* opw  = (const float*)d_in[10];
    const float* opb  = (const float*)d_in[11];
    float* out = (float*)d_out;

    float *xr, *xc, *xdbl, *dlt, *z, *xt, *ipt, *xpt, *dpt, *opt;
    cudaGetSymbolAddress((void**)&xr,   g_xr);
    cudaGetSymbolAddress((void**)&xc,   g_xc);
    cudaGetSymbolAddress((void**)&xdbl, g_xdbl);
    cudaGetSymbolAddress((void**)&dlt,  g_dlt);
    cudaGetSymbolAddress((void**)&z,    g_z);
    cudaGetSymbolAddress((void**)&xt,   g_xt);
    cudaGetSymbolAddress((void**)&ipt,  g_ipt);
    cudaGetSymbolAddress((void**)&xpt,  g_xpt);
    cudaGetSymbolAddress((void**)&dpt,  g_dpt);
    cudaGetSymbolAddress((void**)&opt,  g_opt);

    constexpr int SM128 = 3 * (128 * 144 + 128 * 144);  // 110592
    constexpr int SM32  = 3 * (128 * 144 + 32 * 144);   // 69120
    constexpr int SMEM_SCAN = (6 * ST * 64 + 2 * ST * 32) * 4; // 114688
    cudaFuncSetAttribute((const void*)gemm_tf<128,128,2,4,0,0>, cudaFuncAttributeMaxDynamicSharedMemorySize, SM128);
    cudaFuncSetAttribute((const void*)gemm_tf<128,128,2,4,1,0>, cudaFuncAttributeMaxDynamicSharedMemorySize, SM128);
    cudaFuncSetAttribute((const void*)gemm_tf<128,32,8,1,0,1>,  cudaFuncAttributeMaxDynamicSharedMemorySize, SM32);
    cudaFuncSetAttribute((const void*)scan_k, cudaFuncAttributeMaxDynamicSharedMemorySize, SMEM_SCAN);

    // launch order: in_proj at index 3 (the ncu capture consistently profiles index 3)
    round_k<<<(MTOT*DMODEL/4+255)/256, 256>>>((const float4*)x, (float4*)xt, MTOT*DMODEL/4);        // 0
    round_k<<<(2*DINNER*DMODEL/4+255)/256, 256>>>((const float4*)ipw, (float4*)ipt, 2*DINNER*DMODEL/4); // 1
    round_k<<<(XPDIM*DINNER/4+255)/256, 256>>>((const float4*)xpw, (float4*)xpt, XPDIM*DINNER/4);   // 2

    // in_proj (PROFILED @ index 3): 128x128, frag-double-buffered mainloop     // 3
    gemm_tf<128,128,2,4,0,0><<<dim3(2*DINNER/128, MTOT/128), 256, SM128>>>(
        xt, DMODEL, ipt, DMODEL, xr, 2*DINNER, ipb, DMODEL);

    conv_k<<<MTOT, 256>>>(xr, cw, cb, xc);                                      // 4
    round_k<<<(DINNER*DTRANK/4+255)/256, 256>>>((const float4*)dpw, (float4*)dpt, DINNER*DTRANK/4); // 5

    // x_proj                                                                   // 6
    gemm_tf<128,32,8,1,0,1><<<dim3(XPDIM/32, MTOT/128), 256, SM32>>>(
        xc, DINNER, xpt, DINNER, xdbl, XPDIM, nullptr, DINNER);

    // dt_proj + softplus                                                       // 7
    gemm_tf<128,128,2,4,1,0><<<dim3(DINNER/128, MTOT/128), 256, SM128>>>(
        xdbl, XPDIM, dpt, DTRANK, dlt, DINNER, dpb, DTRANK);

    round_k<<<(DMODEL*DINNER/4+255)/256, 256>>>((const float4*)opw, (float4*)opt, DMODEL*DINNER/4); // 8
    scan_k<<<BB*(DINNER/SCD), SCD, SMEM_SCAN>>>(xdbl, dlt, xc, xr, alog, dvec, z);                  // 9

    // out_proj                                                                 // 10
    gemm_tf<128,128,2,4,0,0><<<dim3(DMODEL/128, MTOT/128), 256, SM128>>>(
        z, DINNER, opt, DINNER, out, DMODEL, opb, DINNER);
}

// round 13
// speedup vs baseline: 1.2167x; 1.0727x over previous
#include <cuda_runtime.h>
#include <cuda_bf16.h>
#include <cstdint>
#include <math.h>

#define BB 4
#define LSEQ 2048
#define DMODEL 1024
#define DINNER 2048
#define DSTATE 16
#define DTRANK 128
#define XPDIM 160
#define MTOT (BB*LSEQ)      // 8192
#define NSEG 8
#define SEGLEN (LSEQ/NSEG)  // 256
#define NCH (BB*DINNER)     // 8192 channels

// ---------------- scratch ----------------------------------------------------
static __device__ float g_xr  [(size_t)MTOT * 2 * DINNER];
static __device__ float g_xc  [(size_t)MTOT * DINNER];
static __device__ float g_xdbl[(size_t)MTOT * XPDIM];
static __device__ float g_dlt [(size_t)MTOT * DINNER];
static __device__ float g_z   [(size_t)MTOT * DINNER];
static __device__ float g_xt  [(size_t)MTOT * DMODEL];
static __device__ float g_ipt [(size_t)2*DINNER * DMODEL];
static __device__ float g_xpt [(size_t)XPDIM * DINNER];
static __device__ float g_dpt [(size_t)DINNER * DTRANK];
static __device__ float g_opt [(size_t)DMODEL * DINNER];
// segmented-scan intermediates
static __device__ float g_hloc[(size_t)NSEG * NCH * DSTATE];
static __device__ float g_S   [(size_t)NSEG * NCH];
static __device__ float g_hin [(size_t)NSEG * NCH * DSTATE];

// ---------------- PTX helpers ------------------------------------------------
__device__ __forceinline__ uint32_t smem_u32(const void* p) {
    uint32_t a;
    asm("{ .reg .u64 t; cvta.to.shared.u64 t, %1; cvt.u32.u64 %0, t; }" : "=r"(a) : "l"(p));
    return a;
}
__device__ __forceinline__ void cpa16(uint32_t s, const void* g) {
    asm volatile("cp.async.cg.shared.global [%0], [%1], 16;" :: "r"(s), "l"(g));
}
#define CP_COMMIT() asm volatile("cp.async.commit_group;" ::: "memory")
#define CP_WAIT(n)  asm volatile("cp.async.wait_group %0;" :: "n"(n) : "memory")

__device__ __forceinline__ void ldsm4(uint32_t* r, uint32_t a) {
    asm volatile("ldmatrix.sync.aligned.m8n8.x4.shared.b16 {%0,%1,%2,%3}, [%4];"
                 : "=r"(r[0]), "=r"(r[1]), "=r"(r[2]), "=r"(r[3]) : "r"(a));
}
__device__ __forceinline__ void ldsm2(uint32_t* r, uint32_t a) {
    asm volatile("ldmatrix.sync.aligned.m8n8.x2.shared.b16 {%0,%1}, [%2];"
                 : "=r"(r[0]), "=r"(r[1]) : "r"(a));
}
__device__ __forceinline__ void mma1688(float* d, const uint32_t* a, const uint32_t* b) {
    asm volatile(
        "mma.sync.aligned.m16n8k8.row.col.f32.tf32.tf32.f32 "
        "{%0,%1,%2,%3}, {%4,%5,%6,%7}, {%8,%9}, {%0,%1,%2,%3};"
        : "+f"(d[0]), "+f"(d[1]), "+f"(d[2]), "+f"(d[3])
        : "r"(a[0]), "r"(a[1]), "r"(a[2]), "r"(a[3]), "r"(b[0]), "r"(b[1]));
}
__device__ __forceinline__ float rtf(float v) {
    uint32_t r;
    asm("cvt.rna.tf32.f32 %0, %1;" : "=r"(r) : "f"(v));
    return __uint_as_float(r);
}

__global__ void round_k(const float4* __restrict__ in, float4* __restrict__ out, int n4) {
    int i = blockIdx.x * blockDim.x + threadIdx.x;
    if (i < n4) {
        float4 v = in[i];
        v.x = rtf(v.x); v.y = rtf(v.y); v.z = rtf(v.z); v.w = rtf(v.w);
        out[i] = v;
    }
}

// ---------------- tf32 HMMA GEMM (R12-proven: 3-stage ring + frag dbl-buf) ---
template<int BM, int BN, int WARPS_M, int WARPS_N, int EPI, int RND>
__global__ void __launch_bounds__(WARPS_M * WARPS_N * 32)
gemm_tf(const float* __restrict__ A, int lda,
        const float* __restrict__ B, int ldb,
        float* __restrict__ C, int ldc, const float* __restrict__ bias, int K)
{
    constexpr int NT = WARPS_M * WARPS_N * 32;
    constexpr int RS = 144;
    constexpr int SA = BM * RS;
    constexpr int SB = BN * RS;
    constexpr int STAGE = SA + SB;
    constexpr int WM = BM / WARPS_M, WN = BN / WARPS_N;
    constexpr int IM = WM / 16, JN = WN / 8;

    extern __shared__ char smem[];
    const uint32_t sbase = smem_u32(smem);
    const int tid = threadIdx.x;
    const int warp = tid >> 5, lane = tid & 31;
    const int wm0 = (warp / WARPS_N) * WM;
    const int wn0 = (warp % WARPS_N) * WN;
    const int m0 = blockIdx.y * BM, n0 = blockIdx.x * BN;
    const int NCC = K >> 5;

    float acc[IM][JN][4];
#pragma unroll
    for (int i = 0; i < IM; i++)
#pragma unroll
        for (int j = 0; j < JN; j++)
#pragma unroll
            for (int q = 0; q < 4; q++) acc[i][j][q] = 0.f;

    auto load_chunk = [&](int kc, int buf) {
        const int k0 = kc << 5;
        const uint32_t st = sbase + buf * STAGE;
        for (int idx = tid; idx < BM * 8; idx += NT) {
            int r = idx >> 3, c = idx & 7;
            cpa16(st + (uint32_t)(r * RS + c * 16), A + (size_t)(m0 + r) * lda + k0 + c * 4);
        }
        for (int idx = tid; idx < BN * 8; idx += NT) {
            int r = idx >> 3, c = idx & 7;
            cpa16(st + SA + (uint32_t)(r * RS + c * 16), B + (size_t)(n0 + r) * ldb + k0 + c * 4);
        }
        CP_COMMIT();
    };

    const uint32_t a_row  = (uint32_t)(wm0 + (lane & 15));
    const uint32_t a_half = (uint32_t)((lane >> 4) * 16);
    const uint32_t b_row  = (uint32_t)(wn0 + (lane & 7));
    const uint32_t b_half = (uint32_t)(((lane >> 3) & 1) * 16);

    load_chunk(0, 0);
    if (NCC > 1) load_chunk(1, 1);

    int buf = 0;
    for (int i = 0; i < NCC; i++) {
        if (i + 1 < NCC) CP_WAIT(1); else CP_WAIT(0);
        __syncthreads();
        if (i + 2 < NCC) load_chunk(i + 2, (buf + 2 >= 3) ? buf - 1 : buf + 2);

        const uint32_t st = sbase + buf * STAGE;
        uint32_t af[2][IM][4], bf[2][JN][2];

        auto ldfrag = [&](int ks, int p) {
#pragma unroll
            for (int im = 0; im < IM; im++)
                ldsm4(af[p][im], st + (a_row + im * 16) * RS + ks * 32 + a_half);
#pragma unroll
            for (int jn = 0; jn < JN; jn++)
                ldsm2(bf[p][jn], st + SA + (b_row + jn * 8) * RS + ks * 32 + b_half);
        };

        ldfrag(0, 0);
#pragma unroll
        for (int ks = 0; ks < 4; ks++) {
            const int cur = ks & 1;
            if (ks < 3) ldfrag(ks + 1, cur ^ 1);
#pragma unroll
            for (int im = 0; im < IM; im++)
#pragma unroll
                for (int jn = 0; jn < JN; jn++)
                    mma1688(acc[im][jn], af[cur][im], bf[cur][jn]);
        }
        buf = (buf + 1 == 3) ? 0 : buf + 1;
    }

#pragma unroll
    for (int im = 0; im < IM; im++) {
#pragma unroll
        for (int jn = 0; jn < JN; jn++) {
            int r = m0 + wm0 + im * 16 + (lane >> 2);
            int c = n0 + wn0 + jn * 8 + (lane & 3) * 2;
#pragma unroll
            for (int half = 0; half < 2; half++) {
                int rr = r + half * 8;
                float t0 = acc[im][jn][half * 2 + 0];
                float t1 = acc[im][jn][half * 2 + 1];
                if (bias) { t0 += bias[c]; t1 += bias[c + 1]; }
                if (EPI == 1) {
                    t0 = fmaxf(t0, 0.f) + log1pf(expf(-fabsf(t0)));
                    t1 = fmaxf(t1, 0.f) + log1pf(expf(-fabsf(t1)));
                }
                if (RND) { t0 = rtf(t0); t1 = rtf(t1); }
                *(float2*)(C + (size_t)rr * ldc + c) = make_float2(t0, t1);
            }
        }
    }
}

// ---------------- depthwise conv1d ------------------------------------------
__global__ void __launch_bounds__(256)
conv_k(const float* __restrict__ xr, const float* __restrict__ w,
       const float* __restrict__ cb, float* __restrict__ out)
{
    const int m = blockIdx.x;
    const int t = m & (LSEQ - 1);
    const size_t rowb = (size_t)m * (2 * DINNER);
    const bool hm1 = (t >= 1), hp1 = (t <= LSEQ - 2), hp2 = (t <= LSEQ - 3);

#pragma unroll
    for (int g = 0; g < 2; g++) {
        const int d = (threadIdx.x + g * 256) * 4;
        float4 wv0 = *(const float4*)(w + (size_t)(d + 0) * 4);
        float4 wv1 = *(const float4*)(w + (size_t)(d + 1) * 4);
        float4 wv2 = *(const float4*)(w + (size_t)(d + 2) * 4);
        float4 wv3 = *(const float4*)(w + (size_t)(d + 3) * 4);
        float4 bv = *(const float4*)(cb + d);

        float4 xm1 = hm1 ? *(const float4*)(xr + rowb - 2 * DINNER + d) : make_float4(0,0,0,0);
        float4 x0  = *(const float4*)(xr + rowb + d);
        float4 xp1 = hp1 ? *(const float4*)(xr + rowb + 2 * DINNER + d) : make_float4(0,0,0,0);
        float4 xp2 = hp2 ? *(const float4*)(xr + rowb + 4 * DINNER + d) : make_float4(0,0,0,0);

        float4 o;
        o.x = rtf(bv.x + wv0.x * xm1.x + wv0.y * x0.x + wv0.z * xp1.x + wv0.w * xp2.x);
        o.y = rtf(bv.y + wv1.x * xm1.y + wv1.y * x0.y + wv1.z * xp1.y + wv1.w * xp2.y);
        o.z = rtf(bv.z + wv2.x * xm1.z + wv2.y * x0.z + wv2.z * xp1.z + wv2.w * xp2.z);
        o.w = rtf(bv.w + wv3.x * xm1.w + wv3.y * x0.w + wv3.z * xp1.w + wv3.w * xp2.w);
        *(float4*)(out + (size_t)m * DINNER + d) = o;
    }
}

// ---------------- segmented selective scan -----------------------------------
// PASS 1: local scan (h_in = 0) over one segment; emit h_loc[16] + S = sum(delta)
// PASS 3: scan seeded with h_in; compute y, D-skip, silu gate, write z
#define ST 64
#define SCD 64
template<int PASS>
__global__ void __launch_bounds__(SCD)
scan_seg(const float* __restrict__ xdbl, const float* __restrict__ delta,
         const float* __restrict__ u, const float* __restrict__ xr,
         const float* __restrict__ Alog, const float* __restrict__ Dp,
         float* __restrict__ z,
         float* __restrict__ hloc, float* __restrict__ Ssum,
         const float* __restrict__ hin)
{
    extern __shared__ float sm[];
    float* sD  = sm;                 // [2][ST*64]
    float* sU  = sm + 2 * ST * 64;
    float* sR  = sm + 4 * ST * 64;   // only staged in PASS 3
    float* sBC = sm + 6 * ST * 64;   // [2][ST*32]
    const uint32_t sbase = smem_u32(sm);

    const int tid = threadIdx.x;
    const int s   = blockIdx.x >> 7;            // segment 0..7
    const int rem = blockIdx.x & 127;
    const int b   = rem >> 5;                   // batch 0..3  (32 d-blocks/batch)
    const int d0  = (rem & 31) * SCD;
    const int d   = d0 + tid;
    const int ch  = b * DINNER + d;

    float a[DSTATE];
#pragma unroll
    for (int n = 0; n < DSTATE; n++) a[n] = -__expf(Alog[d * DSTATE + n]);
    bool geo = true;
#pragma unroll
    for (int n = 1; n < DSTATE; n++)
        geo = geo && (fabsf(a[n] - (float)(n + 1) * a[0]) <= 1e-4f * (float)(n + 1) * fabsf(a[0]));

    const float dd = Dp[d];
    float h[DSTATE];
    if (PASS == 3) {
#pragma unroll
        for (int n = 0; n < DSTATE; n++) h[n] = hin[((size_t)s * NCH + ch) * DSTATE + n];
    } else {
#pragma unroll
        for (int n = 0; n < DSTATE; n++) h[n] = 0.f;
    }
    float S = 0.f;

    auto stage = [&](int c, int bufi) {
        const int t0 = s * SEGLEN + c * ST;
        for (int i = tid; i < ST * 16; i += SCD) {
            int t = i >> 4, q = i & 15;
            size_t m = (size_t)(b * LSEQ + t0 + t);
            uint32_t so = (uint32_t)((bufi * ST * 64 + t * 64 + q * 4) * 4);
            cpa16(sbase + so, delta + m * DINNER + d0 + q * 4);
            cpa16(sbase + 2 * ST * 64 * 4 + so, u + m * DINNER + d0 + q * 4);
            if (PASS == 3)
                cpa16(sbase + 4 * ST * 64 * 4 + so, xr + m * (2 * DINNER) + DINNER + d0 + q * 4);
        }
        for (int i = tid; i < ST * 8; i += SCD) {
            int t = i >> 3, q = i & 7;
            uint32_t so = (uint32_t)(6 * ST * 64 * 4 + (bufi * ST * 32 + t * 32 + q * 4) * 4);
            cpa16(sbase + so, xdbl + (size_t)(b * LSEQ + t0 + t) * XPDIM + DTRANK + q * 4);
        }
        CP_COMMIT();
    };

    const int NCHK = SEGLEN / ST;   // 4
    stage(0, 0);
    for (int c = 0; c < NCHK; c++) {
        const int bufi = c & 1;
        if (c + 1 < NCHK) { stage(c + 1, (c + 1) & 1); CP_WAIT(1); }
        else              { CP_WAIT(0); }
        __syncthreads();

        const float* pD  = sD  + bufi * ST * 64;
        const float* pU  = sU  + bufi * ST * 64;
        const float* pR  = sR  + bufi * ST * 64;
        const float* pBC = sBC + bufi * ST * 32;

        for (int tt = 0; tt < ST; tt++) {
            float dlt = pD[tt * 64 + tid];
            float uu  = pU[tt * 64 + tid];
            float du = dlt * uu;
            if (PASS == 1) S += dlt;

            float bv[DSTATE], cv[DSTATE];
#pragma unroll
            for (int q = 0; q < 4; q++) {
                float4 vb = *(const float4*)(pBC + tt * 32 + q * 4);
                bv[q*4+0]=vb.x; bv[q*4+1]=vb.y; bv[q*4+2]=vb.z; bv[q*4+3]=vb.w;
                float4 vc = *(const float4*)(pBC + tt * 32 + 16 + q * 4);
                cv[q*4+0]=vc.x; cv[q*4+1]=vc.y; cv[q*4+2]=vc.z; cv[q*4+3]=vc.w;
            }

            float y0 = 0.f, y1 = 0.f, y2 = 0.f, y3 = 0.f;
            if (geo) {
                float p[DSTATE];
                p[0] = __expf(dlt * a[0]);
#pragma unroll
                for (int n = 1; n < DSTATE; n++) p[n] = p[(n - 1) >> 1] * p[n >> 1];
#pragma unroll
                for (int n = 0; n < DSTATE; n++) {
                    h[n] = p[n] * h[n] + du * bv[n];
                    if (PASS == 3) {
                        float t = h[n] * cv[n];
                        if ((n & 3) == 0) y0 += t; else if ((n & 3) == 1) y1 += t;
                        else if ((n & 3) == 2) y2 += t; else y3 += t;
                    }
                }
            } else {
#pragma unroll
                for (int n = 0; n < DSTATE; n++) {
                    float dA = __expf(dlt * a[n]);
                    h[n] = dA * h[n] + du * bv[n];
                    if (PASS == 3) {
                        float t = h[n] * cv[n];
                        if ((n & 3) == 0) y0 += t; else if ((n & 3) == 1) y1 += t;
                        else if ((n & 3) == 2) y2 += t; else y3 += t;
                    }
                }
            }

            if (PASS == 3) {
                float y = (y0 + y1) + (y2 + y3) + uu * dd;
                float rr = pR[tt * 64 + tid];
                float sg = 1.f / (1.f + __expf(-rr));
                size_t m = (size_t)(b * LSEQ + s * SEGLEN + c * ST + tt);
                z[m * DINNER + d] = rtf(y * (rr * sg));
            }
        }
        __syncthreads();
    }

    if (PASS == 1) {
#pragma unroll
        for (int n = 0; n < DSTATE; n++)
            hloc[((size_t)s * NCH + ch) * DSTATE + n] = h[n];
        Ssum[(size_t)s * NCH + ch] = S;
    }
}

// Pass 2: per-channel sequential propagation across NSEG segments
__global__ void __launch_bounds__(256)
scan_prop(const float* __restrict__ Alog,
          const float* __restrict__ hloc, const float* __restrict__ Ssum,
          float* __restrict__ hin)
{
    int ch = blockIdx.x * blockDim.x + threadIdx.x;
    if (ch >= NCH) return;
    int d = ch & (DINNER - 1);

    float a[DSTATE];
#pragma unroll
    for (int n = 0; n < DSTATE; n++) a[n] = -__expf(Alog[d * DSTATE + n]);

    float h[DSTATE];
#pragma unroll
    for (int n = 0; n < DSTATE; n++) h[n] = 0.f;

    for (int s = 0; s < NSEG; s++) {
#pragma unroll
        for (int n = 0; n < DSTATE; n++)
            hin[((size_t)s * NCH + ch) * DSTATE + n] = h[n];
        float S = Ssum[(size_t)s * NCH + ch];
#pragma unroll
        for (int n = 0; n < DSTATE; n++)
            h[n] = __expf(a[n] * S) * h[n] + hloc[((size_t)s * NCH + ch) * DSTATE + n];
    }
}

// ---------------- launch -----------------------------------------------------
extern "C" void kernel_launch(void* const* d_in, const int* in_sizes, int n_in,
                              void* d_out, int out_size)
{
    (void)in_sizes; (void)n_in; (void)out_size;
    const float* x    = (const float*)d_in[0];
    const float* ipw  = (const float*)d_in[1];
    const float* ipb  = (const float*)d_in[2];
    const float* cw   = (const float*)d_in[3];
    const float* cb   = (const float*)d_in[4];
    const float* xpw  = (const float*)d_in[5];
    const float* dpw  = (const float*)d_in[6];
    const float* dpb  = (const float*)d_in[7];
    const float* alog = (const float*)d_in[8];
    const float* dvec = (const float*)d_in[9];
    const float* opw  = (const float*)d_in[10];
    const float* opb  = (const float*)d_in[11];
    float* out = (float*)d_out;

    float *xr, *xc, *xdbl, *dlt, *z, *xt, *ipt, *xpt, *dpt, *opt, *hloc, *Ss, *hin;
    cudaGetSymbolAddress((void**)&xr,   g_xr);
    cudaGetSymbolAddress((void**)&xc,   g_xc);
    cudaGetSymbolAddress((void**)&xdbl, g_xdbl);
    cudaGetSymbolAddress((void**)&dlt,  g_dlt);
    cudaGetSymbolAddress((void**)&z,    g_z);
    cudaGetSymbolAddress((void**)&xt,   g_xt);
    cudaGetSymbolAddress((void**)&ipt,  g_ipt);
    cudaGetSymbolAddress((void**)&xpt,  g_xpt);
    cudaGetSymbolAddress((void**)&dpt,  g_dpt);
    cudaGetSymbolAddress((void**)&opt,  g_opt);
    cudaGetSymbolAddress((void**)&hloc, g_hloc);
    cudaGetSymbolAddress((void**)&Ss,   g_S);
    cudaGetSymbolAddress((void**)&hin,  g_hin);

    constexpr int SM128 = 3 * (128 * 144 + 128 * 144);  // 110592
    constexpr int SM32  = 3 * (128 * 144 + 32 * 144);   // 69120
    constexpr int SMEM_SCAN = (6 * ST * 64 + 2 * ST * 32) * 4; // 114688
    cudaFuncSetAttribute((const void*)gemm_tf<128,128,2,4,0,0>, cudaFuncAttributeMaxDynamicSharedMemorySize, SM128);
    cudaFuncSetAttribute((const void*)gemm_tf<128,128,2,4,1,0>, cudaFuncAttributeMaxDynamicSharedMemorySize, SM128);
    cudaFuncSetAttribute((const void*)gemm_tf<128,32,8,1,0,1>,  cudaFuncAttributeMaxDynamicSharedMemorySize, SM32);
    cudaFuncSetAttribute((const void*)scan_seg<1>, cudaFuncAttributeMaxDynamicSharedMemorySize, SMEM_SCAN);
    cudaFuncSetAttribute((const void*)scan_seg<3>, cudaFuncAttributeMaxDynamicSharedMemorySize, SMEM_SCAN);

    round_k<<<(MTOT*DMODEL/4+255)/256, 256>>>((const float4*)x, (float4*)xt, MTOT*DMODEL/4);        // 0
    round_k<<<(2*DINNER*DMODEL/4+255)/256, 256>>>((const float4*)ipw, (float4*)ipt, 2*DINNER*DMODEL/4); // 1
    round_k<<<(XPDIM*DINNER/4+255)/256, 256>>>((const float4*)xpw, (float4*)xpt, XPDIM*DINNER/4);   // 2

    // in_proj (PROFILED @ index 3)                                             // 3
    gemm_tf<128,128,2,4,0,0><<<dim3(2*DINNER/128, MTOT/128), 256, SM128>>>(
        xt, DMODEL, ipt, DMODEL, xr, 2*DINNER, ipb, DMODEL);

    conv_k<<<MTOT, 256>>>(xr, cw, cb, xc);                                      // 4
    round_k<<<(DINNER*DTRANK/4+255)/256, 256>>>((const float4*)dpw, (float4*)dpt, DINNER*DTRANK/4); // 5

    // x_proj                                                                   // 6
    gemm_tf<128,32,8,1,0,1><<<dim3(XPDIM/32, MTOT/128), 256, SM32>>>(
        xc, DINNER, xpt, DINNER, xdbl, XPDIM, nullptr, DINNER);

    // dt_proj + softplus                                                       // 7
    gemm_tf<128,128,2,4,1,0><<<dim3(DINNER/128, MTOT/128), 256, SM128>>>(
        xdbl, XPDIM, dpt, DTRANK, dlt, DINNER, dpb, DTRANK);

    round_k<<<(DMODEL*DINNER/4+255)/256, 256>>>((const float4*)opw, (float4*)opt, DMODEL*DINNER/4); // 8

    // segmented scan: pass1 (local scans) -> pass2 (propagate) -> pass3 (emit z)
    scan_seg<1><<<NSEG * 128, SCD, SMEM_SCAN>>>(xdbl, dlt, xc, xr, alog, dvec,
                                                z, hloc, Ss, nullptr);          // 9
    scan_prop<<<NCH / 256, 256>>>(alog, hloc, Ss, hin);                         // 10
    scan_seg<3><<<NSEG * 128, SCD, SMEM_SCAN>>>(xdbl, dlt, xc, xr, alog, dvec,
                                                z, nullptr, nullptr, hin);      // 11

    // out_proj                                                                 // 12
    gemm_tf<128,128,2,4,0,0><<<dim3(DMODEL/128, MTOT/128), 256, SM128>>>(
        z, DINNER, opt, DINNER, out, DMODEL, opb, DINNER);
}

// round 15
// speedup vs baseline: 1.2207x; 1.0033x over previous
#include <cuda_runtime.h>
#include <cuda_bf16.h>
#include <cstdint>
#include <math.h>

#define BB 4
#define LSEQ 2048
#define DMODEL 1024
#define DINNER 2048
#define DSTATE 16
#define DTRANK 128
#define XPDIM 160
#define MTOT (BB*LSEQ)      // 8192
#define NSEG 8
#define SEGLEN (LSEQ/NSEG)  // 256
#define NCH (BB*DINNER)     // 8192 channels

// ---------------- scratch ----------------------------------------------------
static __device__ float g_xr  [(size_t)MTOT * 2 * DINNER];
static __device__ float g_xc  [(size_t)MTOT * DINNER];
static __device__ float g_xdbl[(size_t)MTOT * XPDIM];
static __device__ float g_dlt [(size_t)MTOT * DINNER];
static __device__ float g_z   [(size_t)MTOT * DINNER];
static __device__ float g_xt  [(size_t)MTOT * DMODEL];
static __device__ float g_ipt [(size_t)2*DINNER * DMODEL];
static __device__ float g_xpt [(size_t)XPDIM * DINNER];
static __device__ float g_dpt [(size_t)DINNER * DTRANK];
static __device__ float g_opt [(size_t)DMODEL * DINNER];
// segmented-scan intermediates
static __device__ float g_hloc[(size_t)NSEG * NCH * DSTATE];
static __device__ float g_S   [(size_t)NSEG * NCH];
static __device__ float g_hin [(size_t)NSEG * NCH * DSTATE];

// ---------------- PTX helpers ------------------------------------------------
__device__ __forceinline__ uint32_t smem_u32(const void* p) {
    uint32_t a;
    asm("{ .reg .u64 t; cvta.to.shared.u64 t, %1; cvt.u32.u64 %0, t; }" : "=r"(a) : "l"(p));
    return a;
}
__device__ __forceinline__ void cpa16(uint32_t s, const void* g) {
    asm volatile("cp.async.cg.shared.global [%0], [%1], 16;" :: "r"(s), "l"(g));
}
#define CP_COMMIT() asm volatile("cp.async.commit_group;" ::: "memory")
#define CP_WAIT(n)  asm volatile("cp.async.wait_group %0;" :: "n"(n) : "memory")

__device__ __forceinline__ void ldsm4(uint32_t* r, uint32_t a) {
    asm volatile("ldmatrix.sync.aligned.m8n8.x4.shared.b16 {%0,%1,%2,%3}, [%4];"
                 : "=r"(r[0]), "=r"(r[1]), "=r"(r[2]), "=r"(r[3]) : "r"(a));
}
__device__ __forceinline__ void ldsm2(uint32_t* r, uint32_t a) {
    asm volatile("ldmatrix.sync.aligned.m8n8.x2.shared.b16 {%0,%1}, [%2];"
                 : "=r"(r[0]), "=r"(r[1]) : "r"(a));
}
__device__ __forceinline__ void mma1688(float* d, const uint32_t* a, const uint32_t* b) {
    asm volatile(
        "mma.sync.aligned.m16n8k8.row.col.f32.tf32.tf32.f32 "
        "{%0,%1,%2,%3}, {%4,%5,%6,%7}, {%8,%9}, {%0,%1,%2,%3};"
        : "+f"(d[0]), "+f"(d[1]), "+f"(d[2]), "+f"(d[3])
        : "r"(a[0]), "r"(a[1]), "r"(a[2]), "r"(a[3]), "r"(b[0]), "r"(b[1]));
}
__device__ __forceinline__ float rtf(float v) {
    uint32_t r;
    asm("cvt.rna.tf32.f32 %0, %1;" : "=r"(r) : "f"(v));
    return __uint_as_float(r);
}

__global__ void round_k(const float4* __restrict__ in, float4* __restrict__ out, int n4) {
    int i = blockIdx.x * blockDim.x + threadIdx.x;
    if (i < n4) {
        float4 v = in[i];
        v.x = rtf(v.x); v.y = rtf(v.y); v.z = rtf(v.z); v.w = rtf(v.w);
        out[i] = v;
    }
}

// ---------------- tf32 HMMA GEMM: 2-stage single-sync ring + frag dbl-buf ----
// smem 2 stages (73.7 KB @128x128) -> 2 blocks/SM (regs ~96, 49K RF). Order per
// chunk: wait(0) -> sync -> issue load(i+1) -> compute(i). One sync per chunk;
// load(i+1) overwrites the buffer last read at compute(i-1), fenced by the sync.
template<int BM, int BN, int WARPS_M, int WARPS_N, int EPI, int RND>
__global__ void __launch_bounds__(WARPS_M * WARPS_N * 32)
gemm_tf(const float* __restrict__ A, int lda,
        const float* __restrict__ B, int ldb,
        float* __restrict__ C, int ldc, const float* __restrict__ bias, int K)
{
    constexpr int NT = WARPS_M * WARPS_N * 32;
    constexpr int RS = 144;
    constexpr int SA = BM * RS;
    constexpr int SB = BN * RS;
    constexpr int STAGE = SA + SB;
    constexpr int WM = BM / WARPS_M, WN = BN / WARPS_N;
    constexpr int IM = WM / 16, JN = WN / 8;

    extern __shared__ char smem[];
    const uint32_t sbase = smem_u32(smem);
    const int tid = threadIdx.x;
    const int warp = tid >> 5, lane = tid & 31;
    const int wm0 = (warp / WARPS_N) * WM;
    const int wn0 = (warp % WARPS_N) * WN;
    const int m0 = blockIdx.y * BM, n0 = blockIdx.x * BN;
    const int NCC = K >> 5;

    float acc[IM][JN][4];
#pragma unroll
    for (int i = 0; i < IM; i++)
#pragma unroll
        for (int j = 0; j < JN; j++)
#pragma unroll
            for (int q = 0; q < 4; q++) acc[i][j][q] = 0.f;

    auto load_chunk = [&](int kc, int buf) {
        const int k0 = kc << 5;
        const uint32_t st = sbase + buf * STAGE;
        for (int idx = tid; idx < BM * 8; idx += NT) {
            int r = idx >> 3, c = idx & 7;
            cpa16(st + (uint32_t)(r * RS + c * 16), A + (size_t)(m0 + r) * lda + k0 + c * 4);
        }
        for (int idx = tid; idx < BN * 8; idx += NT) {
            int r = idx >> 3, c = idx & 7;
            cpa16(st + SA + (uint32_t)(r * RS + c * 16), B + (size_t)(n0 + r) * ldb + k0 + c * 4);
        }
        CP_COMMIT();
    };

    const uint32_t a_row  = (uint32_t)(wm0 + (lane & 15));
    const uint32_t a_half = (uint32_t)((lane >> 4) * 16);
    const uint32_t b_row  = (uint32_t)(wn0 + (lane & 7));
    const uint32_t b_half = (uint32_t)(((lane >> 3) & 1) * 16);

    load_chunk(0, 0);
    for (int i = 0; i < NCC; i++) {
        CP_WAIT(0);                      // chunk i resident
        __syncthreads();                 // reads of chunk i-1 complete -> its buf reusable
        if (i + 1 < NCC) load_chunk(i + 1, (i + 1) & 1);

        const uint32_t st = sbase + (i & 1) * STAGE;
        uint32_t af[2][IM][4], bf[2][JN][2];

        auto ldfrag = [&](int ks, int p) {
#pragma unroll
            for (int im = 0; im < IM; im++)
                ldsm4(af[p][im], st + (a_row + im * 16) * RS + ks * 32 + a_half);
#pragma unroll
            for (int jn = 0; jn < JN; jn++)
                ldsm2(bf[p][jn], st + SA + (b_row + jn * 8) * RS + ks * 32 + b_half);
        };

        ldfrag(0, 0);
#pragma unroll
        for (int ks = 0; ks < 4; ks++) {
            const int cur = ks & 1;
            if (ks < 3) ldfrag(ks + 1, cur ^ 1);
#pragma unroll
            for (int im = 0; im < IM; im++)
#pragma unroll
                for (int jn = 0; jn < JN; jn++)
                    mma1688(acc[im][jn], af[cur][im], bf[cur][jn]);
        }
    }

#pragma unroll
    for (int im = 0; im < IM; im++) {
#pragma unroll
        for (int jn = 0; jn < JN; jn++) {
            int r = m0 + wm0 + im * 16 + (lane >> 2);
            int c = n0 + wn0 + jn * 8 + (lane & 3) * 2;
#pragma unroll
            for (int half = 0; half < 2; half++) {
                int rr = r + half * 8;
                float t0 = acc[im][jn][half * 2 + 0];
                float t1 = acc[im][jn][half * 2 + 1];
                if (bias) { t0 += bias[c]; t1 += bias[c + 1]; }
                if (EPI == 1) {
                    t0 = fmaxf(t0, 0.f) + log1pf(expf(-fabsf(t0)));
                    t1 = fmaxf(t1, 0.f) + log1pf(expf(-fabsf(t1)));
                }
                if (RND) { t0 = rtf(t0); t1 = rtf(t1); }
                *(float2*)(C + (size_t)rr * ldc + c) = make_float2(t0, t1);
            }
        }
    }
}

// ---------------- depthwise conv1d ------------------------------------------
__global__ void __launch_bounds__(256)
conv_k(const float* __restrict__ xr, const float* __restrict__ w,
       const float* __restrict__ cb, float* __restrict__ out)
{
    const int m = blockIdx.x;
    const int t = m & (LSEQ - 1);
    const size_t rowb = (size_t)m * (2 * DINNER);
    const bool hm1 = (t >= 1), hp1 = (t <= LSEQ - 2), hp2 = (t <= LSEQ - 3);

#pragma unroll
    for (int g = 0; g < 2; g++) {
        const int d = (threadIdx.x + g * 256) * 4;
        float4 wv0 = *(const float4*)(w + (size_t)(d + 0) * 4);
        float4 wv1 = *(const float4*)(w + (size_t)(d + 1) * 4);
        float4 wv2 = *(const float4*)(w + (size_t)(d + 2) * 4);
        float4 wv3 = *(const float4*)(w + (size_t)(d + 3) * 4);
        float4 bv = *(const float4*)(cb + d);

        float4 xm1 = hm1 ? *(const float4*)(xr + rowb - 2 * DINNER + d) : make_float4(0,0,0,0);
        float4 x0  = *(const float4*)(xr + rowb + d);
        float4 xp1 = hp1 ? *(const float4*)(xr + rowb + 2 * DINNER + d) : make_float4(0,0,0,0);
        float4 xp2 = hp2 ? *(const float4*)(xr + rowb + 4 * DINNER + d) : make_float4(0,0,0,0);

        float4 o;
        o.x = rtf(bv.x + wv0.x * xm1.x + wv0.y * x0.x + wv0.z * xp1.x + wv0.w * xp2.x);
        o.y = rtf(bv.y + wv1.x * xm1.y + wv1.y * x0.y + wv1.z * xp1.y + wv1.w * xp2.y);
        o.z = rtf(bv.z + wv2.x * xm1.z + wv2.y * x0.z + wv2.z * xp1.z + wv2.w * xp2.z);
        o.w = rtf(bv.w + wv3.x * xm1.w + wv3.y * x0.w + wv3.z * xp1.w + wv3.w * xp2.w);
        *(float4*)(out + (size_t)m * DINNER + d) = o;
    }
}

// ---------------- segmented selective scan -----------------------------------
#define ST 64
#define SCD 64
template<int PASS>
__global__ void __launch_bounds__(SCD)
scan_seg(const float* __restrict__ xdbl, const float* __restrict__ delta,
         const float* __restrict__ u, const float* __restrict__ xr,
         const float* __restrict__ Alog, const float* __restrict__ Dp,
         float* __restrict__ z,
         float* __restrict__ hloc, float* __restrict__ Ssum,
         const float* __restrict__ hin)
{
    extern __shared__ float sm[];
    float* sD  = sm;
    float* sU  = sm + 2 * ST * 64;
    float* sR  = sm + 4 * ST * 64;
    float* sBC = sm + 6 * ST * 64;
    const uint32_t sbase = smem_u32(sm);

    const int tid = threadIdx.x;
    const int s   = blockIdx.x >> 7;
    const int rem = blockIdx.x & 127;
    const int b   = rem >> 5;
    const int d0  = (rem & 31) * SCD;
    const int d   = d0 + tid;
    const int ch  = b * DINNER + d;

    float a[DSTATE];
#pragma unroll
    for (int n = 0; n < DSTATE; n++) a[n] = -__expf(Alog[d * DSTATE + n]);
    bool geo = true;
#pragma unroll
    for (int n = 1; n < DSTATE; n++)
        geo = geo && (fabsf(a[n] - (float)(n + 1) * a[0]) <= 1e-4f * (float)(n + 1) * fabsf(a[0]));

    const float dd = Dp[d];
    float h[DSTATE];
    if (PASS == 3) {
#pragma unroll
        for (int n = 0; n < DSTATE; n++) h[n] = hin[((size_t)s * NCH + ch) * DSTATE + n];
    } else {
#pragma unroll
        for (int n = 0; n < DSTATE; n++) h[n] = 0.f;
    }
    float S = 0.f;

    auto stage = [&](int c, int bufi) {
        const int t0 = s * SEGLEN + c * ST;
        for (int i = tid; i < ST * 16; i += SCD) {
            int t = i >> 4, q = i & 15;
            size_t m = (size_t)(b * LSEQ + t0 + t);
            uint32_t so = (uint32_t)((bufi * ST * 64 + t * 64 + q * 4) * 4);
            cpa16(sbase + so, delta + m * DINNER + d0 + q * 4);
            cpa16(sbase + 2 * ST * 64 * 4 + so, u + m * DINNER + d0 + q * 4);
            if (PASS == 3)
                cpa16(sbase + 4 * ST * 64 * 4 + so, xr + m * (2 * DINNER) + DINNER + d0 + q * 4);
        }
        for (int i = tid; i < ST * 8; i += SCD) {
            int t = i >> 3, q = i & 7;
            uint32_t so = (uint32_t)(6 * ST * 64 * 4 + (bufi * ST * 32 + t * 32 + q * 4) * 4);
            cpa16(sbase + so, xdbl + (size_t)(b * LSEQ + t0 + t) * XPDIM + DTRANK + q * 4);
        }
        CP_COMMIT();
    };

    const int NCHK = SEGLEN / ST;
    stage(0, 0);
    for (int c = 0; c < NCHK; c++) {
        const int bufi = c & 1;
        if (c + 1 < NCHK) { stage(c + 1, (c + 1) & 1); CP_WAIT(1); }
        else              { CP_WAIT(0); }
        __syncthreads();

        const float* pD  = sD  + bufi * ST * 64;
        const float* pU  = sU  + bufi * ST * 64;
        const float* pR  = sR  + bufi * ST * 64;
        const float* pBC = sBC + bufi * ST * 32;

        for (int tt = 0; tt < ST; tt++) {
            float dlt = pD[tt * 64 + tid];
            float uu  = pU[tt * 64 + tid];
            float du = dlt * uu;
            if (PASS == 1) S += dlt;

            float bv[DSTATE], cv[DSTATE];
#pragma unroll
            for (int q = 0; q < 4; q++) {
                float4 vb = *(const float4*)(pBC + tt * 32 + q * 4);
                bv[q*4+0]=vb.x; bv[q*4+1]=vb.y; bv[q*4+2]=vb.z; bv[q*4+3]=vb.w;
                float4 vc = *(const float4*)(pBC + tt * 32 + 16 + q * 4);
                cv[q*4+0]=vc.x; cv[q*4+1]=vc.y; cv[q*4+2]=vc.z; cv[q*4+3]=vc.w;
            }

            float y0 = 0.f, y1 = 0.f, y2 = 0.f, y3 = 0.f;
            if (geo) {
                float p[DSTATE];
                p[0] = __expf(dlt * a[0]);
#pragma unroll
                for (int n = 1; n < DSTATE; n++) p[n] = p[(n - 1) >> 1] * p[n >> 1];
#pragma unroll
                for (int n = 0; n < DSTATE; n++) {
                    h[n] = p[n] * h[n] + du * bv[n];
                    if (PASS == 3) {
                        float t = h[n] * cv[n];
                        if ((n & 3) == 0) y0 += t; else if ((n & 3) == 1) y1 += t;
                        else if ((n & 3) == 2) y2 += t; else y3 += t;
                    }
                }
            } else {
#pragma unroll
                for (int n = 0; n < DSTATE; n++) {
                    float dA = __expf(dlt * a[n]);
                    h[n] = dA * h[n] + du * bv[n];
                    if (PASS == 3) {
                        float t = h[n] * cv[n];
                        if ((n & 3) == 0) y0 += t; else if ((n & 3) == 1) y1 += t;
                        else if ((n & 3) == 2) y2 += t; else y3 += t;
                    }
                }
            }

            if (PASS == 3) {
                float y = (y0 + y1) + (y2 + y3) + uu * dd;
                float rr = pR[tt * 64 + tid];
                float sg = 1.f / (1.f + __expf(-rr));
                size_t m = (size_t)(b * LSEQ + s * SEGLEN + c * ST + tt);
                z[m * DINNER + d] = rtf(y * (rr * sg));
            }
        }
        __syncthreads();
    }

    if (PASS == 1) {
#pragma unroll
        for (int n = 0; n < DSTATE; n++)
            hloc[((size_t)s * NCH + ch) * DSTATE + n] = h[n];
        Ssum[(size_t)s * NCH + ch] = S;
    }
}

__global__ void __launch_bounds__(256)
scan_prop(const float* __restrict__ Alog,
          const float* __restrict__ hloc, const float* __restrict__ Ssum,
          float* __restrict__ hin)
{
    int ch = blockIdx.x * blockDim.x + threadIdx.x;
    if (ch >= NCH) return;
    int d = ch & (DINNER - 1);

    float a[DSTATE];
#pragma unroll
    for (int n = 0; n < DSTATE; n++) a[n] = -__expf(Alog[d * DSTATE + n]);

    float h[DSTATE];
#pragma unroll
    for (int n = 0; n < DSTATE; n++) h[n] = 0.f;

    for (int s = 0; s < NSEG; s++) {
#pragma unroll
        for (int n = 0; n < DSTATE; n++)
            hin[((size_t)s * NCH + ch) * DSTATE + n] = h[n];
        float S = Ssum[(size_t)s * NCH + ch];
#pragma unroll
        for (int n = 0; n < DSTATE; n++)
            h[n] = __expf(a[n] * S) * h[n] + hloc[((size_t)s * NCH + ch) * DSTATE + n];
    }
}

// ---------------- launch -----------------------------------------------------
extern "C" void kernel_launch(void* const* d_in, const int* in_sizes, int n_in,
                              void* d_out, int out_size)
{
    (void)in_sizes; (void)n_in; (void)out_size;
    const float* x    = (const float*)d_in[0];
    const float* ipw  = (const float*)d_in[1];
    const float* ipb  = (const float*)d_in[2];
    const float* cw   = (const float*)d_in[3];
    const float* cb   = (const float*)d_in[4];
    const float* xpw  = (const float*)d_in[5];
    const float* dpw  = (const float*)d_in[6];
    const float* dpb  = (const float*)d_in[7];
    const float* alog = (const float*)d_in[8];
    const float* dvec = (const float*)d_in[9];
    const float* opw  = (const float*)d_in[10];
    const float* opb  = (const float*)d_in[11];
    float* out = (float*)d_out;

    float *xr, *xc, *xdbl, *dlt, *z, *xt, *ipt, *xpt, *dpt, *opt, *hloc, *Ss, *hin;
    cudaGetSymbolAddress((void**)&xr,   g_xr);
    cudaGetSymbolAddress((void**)&xc,   g_xc);
    cudaGetSymbolAddress((void**)&xdbl, g_xdbl);
    cudaGetSymbolAddress((void**)&dlt,  g_dlt);
    cudaGetSymbolAddress((void**)&z,    g_z);
    cudaGetSymbolAddress((void**)&xt,   g_xt);
    cudaGetSymbolAddress((void**)&ipt,  g_ipt);
    cudaGetSymbolAddress((void**)&xpt,  g_xpt);
    cudaGetSymbolAddress((void**)&dpt,  g_dpt);
    cudaGetSymbolAddress((void**)&opt,  g_opt);
    cudaGetSymbolAddress((void**)&hloc, g_hloc);
    cudaGetSymbolAddress((void**)&Ss,   g_S);
    cudaGetSymbolAddress((void**)&hin,  g_hin);

    constexpr int SM128 = 2 * (128 * 144 + 128 * 144);  // 73728 -> 2 blocks/SM
    constexpr int SM32  = 2 * (128 * 144 + 32 * 144);   // 46080
    constexpr int SMEM_SCAN = (6 * ST * 64 + 2 * ST * 32) * 4; // 114688
    cudaFuncSetAttribute((const void*)gemm_tf<128,128,2,4,0,0>, cudaFuncAttributeMaxDynamicSharedMemorySize, SM128);
    cudaFuncSetAttribute((const void*)gemm_tf<128,128,2,4,1,0>, cudaFuncAttributeMaxDynamicSharedMemorySize, SM128);
    cudaFuncSetAttribute((const void*)gemm_tf<128,32,8,1,0,1>,  cudaFuncAttributeMaxDynamicSharedMemorySize, SM32);
    cudaFuncSetAttribute((const void*)scan_seg<1>, cudaFuncAttributeMaxDynamicSharedMemorySize, SMEM_SCAN);
    cudaFuncSetAttribute((const void*)scan_seg<3>, cudaFuncAttributeMaxDynamicSharedMemorySize, SMEM_SCAN);

    round_k<<<(MTOT*DMODEL/4+255)/256, 256>>>((const float4*)x, (float4*)xt, MTOT*DMODEL/4);        // 0
    round_k<<<(2*DINNER*DMODEL/4+255)/256, 256>>>((const float4*)ipw, (float4*)ipt, 2*DINNER*DMODEL/4); // 1
    round_k<<<(XPDIM*DINNER/4+255)/256, 256>>>((const float4*)xpw, (float4*)xpt, XPDIM*DINNER/4);   // 2

    // in_proj (PROFILED @ index 3)                                             // 3
    gemm_tf<128,128,2,4,0,0><<<dim3(2*DINNER/128, MTOT/128), 256, SM128>>>(
        xt, DMODEL, ipt, DMODEL, xr, 2*DINNER, ipb, DMODEL);

    conv_k<<<MTOT, 256>>>(xr, cw, cb, xc);                                      // 4
    round_k<<<(DINNER*DTRANK/4+255)/256, 256>>>((const float4*)dpw, (float4*)dpt, DINNER*DTRANK/4); // 5

    // x_proj                                                                   // 6
    gemm_tf<128,32,8,1,0,1><<<dim3(XPDIM/32, MTOT/128), 256, SM32>>>(
        xc, DINNER, xpt, DINNER, xdbl, XPDIM, nullptr, DINNER);

    // dt_proj + softplus                                                       // 7
    gemm_tf<128,128,2,4,1,0><<<dim3(DINNER/128, MTOT/128), 256, SM128>>>(
        xdbl, XPDIM, dpt, DTRANK, dlt, DINNER, dpb, DTRANK);

    round_k<<<(DMODEL*DINNER/4+255)/256, 256>>>((const float4*)opw, (float4*)opt, DMODEL*DINNER/4); // 8

    // segmented scan: pass1 -> pass2 -> pass3
    scan_seg<1><<<NSEG * 128, SCD, SMEM_SCAN>>>(xdbl, dlt, xc, xr, alog, dvec,
                                                z, hloc, Ss, nullptr);          // 9
    scan_prop<<<NCH / 256, 256>>>(alog, hloc, Ss, hin);                         // 10
    scan_seg<3><<<NSEG * 128, SCD, SMEM_SCAN>>>(xdbl, dlt, xc, xr, alog, dvec,
                                                z, nullptr, nullptr, hin);      // 11

    // out_proj                                                                 // 12
    gemm_tf<128,128,2,4,0,0><<<dim3(DMODEL/128, MTOT/128), 256, SM128>>>(
        z, DINNER, opt, DINNER, out, DMODEL, opb, DINNER);
}

// round 16
// speedup vs baseline: 1.2272x; 1.0053x over previous
#include <cuda_runtime.h>
#include <cuda_bf16.h>
#include <cstdint>
#include <math.h>

#define BB 4
#define LSEQ 2048
#define DMODEL 1024
#define DINNER 2048
#define DSTATE 16
#define DTRANK 128
#define XPDIM 160
#define MTOT (BB*LSEQ)      // 8192
#define NSEG 8
#define SEGLEN (LSEQ/NSEG)  // 256
#define NCH (BB*DINNER)     // 8192 channels

// ---------------- scratch ----------------------------------------------------
static __device__ float g_xr  [(size_t)MTOT * 2 * DINNER];
static __device__ float g_xc  [(size_t)MTOT * DINNER];
static __device__ float g_xdbl[(size_t)MTOT * XPDIM];
static __device__ float g_dlt [(size_t)MTOT * DINNER];
static __device__ float g_z   [(size_t)MTOT * DINNER];
static __device__ float g_xt  [(size_t)MTOT * DMODEL];
static __device__ float g_ipt [(size_t)2*DINNER * DMODEL];
static __device__ float g_xpt [(size_t)XPDIM * DINNER];
static __device__ float g_dpt [(size_t)DINNER * DTRANK];
static __device__ float g_opt [(size_t)DMODEL * DINNER];
// segmented-scan intermediates
static __device__ float g_hloc[(size_t)NSEG * NCH * DSTATE];
static __device__ float g_S   [(size_t)NSEG * NCH];
static __device__ float g_hin [(size_t)NSEG * NCH * DSTATE];

// ---------------- PTX helpers ------------------------------------------------
__device__ __forceinline__ uint32_t smem_u32(const void* p) {
    uint32_t a;
    asm("{ .reg .u64 t; cvta.to.shared.u64 t, %1; cvt.u32.u64 %0, t; }" : "=r"(a) : "l"(p));
    return a;
}
__device__ __forceinline__ void cpa16(uint32_t s, const void* g) {
    asm volatile("cp.async.cg.shared.global [%0], [%1], 16;" :: "r"(s), "l"(g));
}
#define CP_COMMIT() asm volatile("cp.async.commit_group;" ::: "memory")
#define CP_WAIT(n)  asm volatile("cp.async.wait_group %0;" :: "n"(n) : "memory")

__device__ __forceinline__ void ldsm4(uint32_t* r, uint32_t a) {
    asm volatile("ldmatrix.sync.aligned.m8n8.x4.shared.b16 {%0,%1,%2,%3}, [%4];"
                 : "=r"(r[0]), "=r"(r[1]), "=r"(r[2]), "=r"(r[3]) : "r"(a));
}
__device__ __forceinline__ void ldsm2(uint32_t* r, uint32_t a) {
    asm volatile("ldmatrix.sync.aligned.m8n8.x2.shared.b16 {%0,%1}, [%2];"
                 : "=r"(r[0]), "=r"(r[1]) : "r"(a));
}
__device__ __forceinline__ void mma1688(float* d, const uint32_t* a, const uint32_t* b) {
    asm volatile(
        "mma.sync.aligned.m16n8k8.row.col.f32.tf32.tf32.f32 "
        "{%0,%1,%2,%3}, {%4,%5,%6,%7}, {%8,%9}, {%0,%1,%2,%3};"
        : "+f"(d[0]), "+f"(d[1]), "+f"(d[2]), "+f"(d[3])
        : "r"(a[0]), "r"(a[1]), "r"(a[2]), "r"(a[3]), "r"(b[0]), "r"(b[1]));
}
__device__ __forceinline__ float rtf(float v) {
    uint32_t r;
    asm("cvt.rna.tf32.f32 %0, %1;" : "=r"(r) : "f"(v));
    return __uint_as_float(r);
}

__global__ void round_k(const float4* __restrict__ in, float4* __restrict__ out, int n4) {
    int i = blockIdx.x * blockDim.x + threadIdx.x;
    if (i < n4) {
        float4 v = in[i];
        v.x = rtf(v.x); v.y = rtf(v.y); v.z = rtf(v.z); v.w = rtf(v.w);
        out[i] = v;
    }
}

// ---------------- tf32 HMMA GEMM: 2-stage single-sync ring + frag dbl-buf ----
// smem 2 stages (73.7 KB @128x128) -> 2 blocks/SM (regs ~96, 49K RF). Order per
// chunk: wait(0) -> sync -> issue load(i+1) -> compute(i). One sync per chunk;
// load(i+1) overwrites the buffer last read at compute(i-1), fenced by the sync.
template<int BM, int BN, int WARPS_M, int WARPS_N, int EPI, int RND>
__global__ void __launch_bounds__(WARPS_M * WARPS_N * 32)
gemm_tf(const float* __restrict__ A, int lda,
        const float* __restrict__ B, int ldb,
        float* __restrict__ C, int ldc, const float* __restrict__ bias, int K)
{
    constexpr int NT = WARPS_M * WARPS_N * 32;
    constexpr int RS = 144;
    constexpr int SA = BM * RS;
    constexpr int SB = BN * RS;
    constexpr int STAGE = SA + SB;
    constexpr int WM = BM / WARPS_M, WN = BN / WARPS_N;
    constexpr int IM = WM / 16, JN = WN / 8;

    extern __shared__ char smem[];
    const uint32_t sbase = smem_u32(smem);
    const int tid = threadIdx.x;
    const int warp = tid >> 5, lane = tid & 31;
    const int wm0 = (warp / WARPS_N) * WM;
    const int wn0 = (warp % WARPS_N) * WN;
    const int m0 = blockIdx.y * BM, n0 = blockIdx.x * BN;
    const int NCC = K >> 5;

    float acc[IM][JN][4];
#pragma unroll
    for (int i = 0; i < IM; i++)
#pragma unroll
        for (int j = 0; j < JN; j++)
#pragma unroll
            for (int q = 0; q < 4; q++) acc[i][j][q] = 0.f;

    auto load_chunk = [&](int kc, int buf) {
        const int k0 = kc << 5;
        const uint32_t st = sbase + buf * STAGE;
        for (int idx = tid; idx < BM * 8; idx += NT) {
            int r = idx >> 3, c = idx & 7;
            cpa16(st + (uint32_t)(r * RS + c * 16), A + (size_t)(m0 + r) * lda + k0 + c * 4);
        }
        for (int idx = tid; idx < BN * 8; idx += NT) {
            int r = idx >> 3, c = idx & 7;
            cpa16(st + SA + (uint32_t)(r * RS + c * 16), B + (size_t)(n0 + r) * ldb + k0 + c * 4);
        }
        CP_COMMIT();
    };

    const uint32_t a_row  = (uint32_t)(wm0 + (lane & 15));
    const uint32_t a_half = (uint32_t)((lane >> 4) * 16);
    const uint32_t b_row  = (uint32_t)(wn0 + (lane & 7));
    const uint32_t b_half = (uint32_t)(((lane >> 3) & 1) * 16);

    load_chunk(0, 0);
    for (int i = 0; i < NCC; i++) {
        CP_WAIT(0);                      // chunk i resident
        __syncthreads();                 // reads of chunk i-1 complete -> its buf reusable
        if (i + 1 < NCC) load_chunk(i + 1, (i + 1) & 1);

        const uint32_t st = sbase + (i & 1) * STAGE;
        uint32_t af[2][IM][4], bf[2][JN][2];

        auto ldfrag = [&](int ks, int p) {
#pragma unroll
            for (int im = 0; im < IM; im++)
                ldsm4(af[p][im], st + (a_row + im * 16) * RS + ks * 32 + a_half);
#pragma unroll
            for (int jn = 0; jn < JN; jn++)
                ldsm2(bf[p][jn], st + SA + (b_row + jn * 8) * RS + ks * 32 + b_half);
        };

        ldfrag(0, 0);
#pragma unroll
        for (int ks = 0; ks < 4; ks++) {
            const int cur = ks & 1;
            if (ks < 3) ldfrag(ks + 1, cur ^ 1);
#pragma unroll
            for (int im = 0; im < IM; im++)
#pragma unroll
                for (int jn = 0; jn < JN; jn++)
                    mma1688(acc[im][jn], af[cur][im], bf[cur][jn]);
        }
    }

#pragma unroll
    for (int im = 0; im < IM; im++) {
#pragma unroll
        for (int jn = 0; jn < JN; jn++) {
            int r = m0 + wm0 + im * 16 + (lane >> 2);
            int c = n0 + wn0 + jn * 8 + (lane & 3) * 2;
#pragma unroll
            for (int half = 0; half < 2; half++) {
                int rr = r + half * 8;
                float t0 = acc[im][jn][half * 2 + 0];
                float t1 = acc[im][jn][half * 2 + 1];
                if (bias) { t0 += bias[c]; t1 += bias[c + 1]; }
                if (EPI == 1) {
                    t0 = fmaxf(t0, 0.f) + log1pf(expf(-fabsf(t0)));
                    t1 = fmaxf(t1, 0.f) + log1pf(expf(-fabsf(t1)));
                }
                if (RND) { t0 = rtf(t0); t1 = rtf(t1); }
                *(float2*)(C + (size_t)rr * ldc + c) = make_float2(t0, t1);
            }
        }
    }
}

// ---------------- depthwise conv1d ------------------------------------------
__global__ void __launch_bounds__(256)
conv_k(const float* __restrict__ xr, const float* __restrict__ w,
       const float* __restrict__ cb, float* __restrict__ out)
{
    const int m = blockIdx.x;
    const int t = m & (LSEQ - 1);
    const size_t rowb = (size_t)m * (2 * DINNER);
    const bool hm1 = (t >= 1), hp1 = (t <= LSEQ - 2), hp2 = (t <= LSEQ - 3);

#pragma unroll
    for (int g = 0; g < 2; g++) {
        const int d = (threadIdx.x + g * 256) * 4;
        float4 wv0 = *(const float4*)(w + (size_t)(d + 0) * 4);
        float4 wv1 = *(const float4*)(w + (size_t)(d + 1) * 4);
        float4 wv2 = *(const float4*)(w + (size_t)(d + 2) * 4);
        float4 wv3 = *(const float4*)(w + (size_t)(d + 3) * 4);
        float4 bv = *(const float4*)(cb + d);

        float4 xm1 = hm1 ? *(const float4*)(xr + rowb - 2 * DINNER + d) : make_float4(0,0,0,0);
        float4 x0  = *(const float4*)(xr + rowb + d);
        float4 xp1 = hp1 ? *(const float4*)(xr + rowb + 2 * DINNER + d) : make_float4(0,0,0,0);
        float4 xp2 = hp2 ? *(const float4*)(xr + rowb + 4 * DINNER + d) : make_float4(0,0,0,0);

        float4 o;
        o.x = rtf(bv.x + wv0.x * xm1.x + wv0.y * x0.x + wv0.z * xp1.x + wv0.w * xp2.x);
        o.y = rtf(bv.y + wv1.x * xm1.y + wv1.y * x0.y + wv1.z * xp1.y + wv1.w * xp2.y);
        o.z = rtf(bv.z + wv2.x * xm1.z + wv2.y * x0.z + wv2.z * xp1.z + wv2.w * xp2.z);
        o.w = rtf(bv.w + wv3.x * xm1.w + wv3.y * x0.w + wv3.z * xp1.w + wv3.w * xp2.w);
        *(float4*)(out + (size_t)m * DINNER + d) = o;
    }
}

// ---------------- segmented selective scan -----------------------------------
#define ST 64
#define SCD 64
template<int PASS>
__global__ void __launch_bounds__(SCD)
scan_seg(const float* __restrict__ xdbl, const float* __restrict__ delta,
         const float* __restrict__ u, const float* __restrict__ xr,
         const float* __restrict__ Alog, const float* __restrict__ Dp,
         float* __restrict__ z,
         float* __restrict__ hloc, float* __restrict__ Ssum,
         const float* __restrict__ hin)
{
    extern __shared__ float sm[];
    float* sD  = sm;
    float* sU  = sm + 2 * ST * 64;
    float* sR  = sm + 4 * ST * 64;
    float* sBC = sm + 6 * ST * 64;
    const uint32_t sbase = smem_u32(sm);

    const int tid = threadIdx.x;
    const int s   = blockIdx.x >> 7;
    const int rem = blockIdx.x & 127;
    const int b   = rem >> 5;
    const int d0  = (rem & 31) * SCD;
    const int d   = d0 + tid;
    const int ch  = b * DINNER + d;

    float a[DSTATE];
#pragma unroll
    for (int n = 0; n < DSTATE; n++) a[n] = -__expf(Alog[d * DSTATE + n]);
    bool geo = true;
#pragma unroll
    for (int n = 1; n < DSTATE; n++)
        geo = geo && (fabsf(a[n] - (float)(n + 1) * a[0]) <= 1e-4f * (float)(n + 1) * fabsf(a[0]));

    const float dd = Dp[d];
    float h[DSTATE];
    if (PASS == 3) {
#pragma unroll
        for (int n = 0; n < DSTATE; n++) h[n] = hin[((size_t)s * NCH + ch) * DSTATE + n];
    } else {
#pragma unroll
        for (int n = 0; n < DSTATE; n++) h[n] = 0.f;
    }
    float S = 0.f;

    auto stage = [&](int c, int bufi) {
        const int t0 = s * SEGLEN + c * ST;
        for (int i = tid; i < ST * 16; i += SCD) {
            int t = i >> 4, q = i & 15;
            size_t m = (size_t)(b * LSEQ + t0 + t);
            uint32_t so = (uint32_t)((bufi * ST * 64 + t * 64 + q * 4) * 4);
            cpa16(sbase + so, delta + m * DINNER + d0 + q * 4);
            cpa16(sbase + 2 * ST * 64 * 4 + so, u + m * DINNER + d0 + q * 4);
            if (PASS == 3)
                cpa16(sbase + 4 * ST * 64 * 4 + so, xr + m * (2 * DINNER) + DINNER + d0 + q * 4);
        }
        for (int i = tid; i < ST * 8; i += SCD) {
            int t = i >> 3, q = i & 7;
            uint32_t so = (uint32_t)(6 * ST * 64 * 4 + (bufi * ST * 32 + t * 32 + q * 4) * 4);
            cpa16(sbase + so, xdbl + (size_t)(b * LSEQ + t0 + t) * XPDIM + DTRANK + q * 4);
        }
        CP_COMMIT();
    };

    const int NCHK = SEGLEN / ST;
    stage(0, 0);
    for (int c = 0; c < NCHK; c++) {
        const int bufi = c & 1;
        if (c + 1 < NCHK) { stage(c + 1, (c + 1) & 1); CP_WAIT(1); }
        else              { CP_WAIT(0); }
        __syncthreads();

        const float* pD  = sD  + bufi * ST * 64;
        const float* pU  = sU  + bufi * ST * 64;
        const float* pR  = sR  + bufi * ST * 64;
        const float* pBC = sBC + bufi * ST * 32;

        for (int tt = 0; tt < ST; tt++) {
            float dlt = pD[tt * 64 + tid];
            float uu  = pU[tt * 64 + tid];
            float du = dlt * uu;
            if (PASS == 1) S += dlt;

            float bv[DSTATE], cv[DSTATE];
#pragma unroll
            for (int q = 0; q < 4; q++) {
                float4 vb = *(const float4*)(pBC + tt * 32 + q * 4);
                bv[q*4+0]=vb.x; bv[q*4+1]=vb.y; bv[q*4+2]=vb.z; bv[q*4+3]=vb.w;
                float4 vc = *(const float4*)(pBC + tt * 32 + 16 + q * 4);
                cv[q*4+0]=vc.x; cv[q*4+1]=vc.y; cv[q*4+2]=vc.z; cv[q*4+3]=vc.w;
            }

            float y0 = 0.f, y1 = 0.f, y2 = 0.f, y3 = 0.f;
            if (geo) {
                float p[DSTATE];
                p[0] = __expf(dlt * a[0]);
#pragma unroll
                for (int n = 1; n < DSTATE; n++) p[n] = p[(n - 1) >> 1] * p[n >> 1];
#pragma unroll
                for (int n = 0; n < DSTATE; n++) {
                    h[n] = p[n] * h[n] + du * bv[n];
                    if (PASS == 3) {
                        float t = h[n] * cv[n];
                        if ((n & 3) == 0) y0 += t; else if ((n & 3) == 1) y1 += t;
                        else if ((n & 3) == 2) y2 += t; else y3 += t;
                    }
                }
            } else {
#pragma unroll
                for (int n = 0; n < DSTATE; n++) {
                    float dA = __expf(dlt * a[n]);
                    h[n] = dA * h[n] + du * bv[n];
                    if (PASS == 3) {
                        float t = h[n] * cv[n];
                        if ((n & 3) == 0) y0 += t; else if ((n & 3) == 1) y1 += t;
                        else if ((n & 3) == 2) y2 += t; else y3 += t;
                    }
                }
            }

            if (PASS == 3) {
                float y = (y0 + y1) + (y2 + y3) + uu * dd;
                float rr = pR[tt * 64 + tid];
                float sg = 1.f / (1.f + __expf(-rr));
                size_t m = (size_t)(b * LSEQ + s * SEGLEN + c * ST + tt);
                z[m * DINNER + d] = rtf(y * (rr * sg));
            }
        }
        __syncthreads();
    }

    if (PASS == 1) {
#pragma unroll
        for (int n = 0; n < DSTATE; n++)
            hloc[((size_t)s * NCH + ch) * DSTATE + n] = h[n];
        Ssum[(size_t)s * NCH + ch] = S;
    }
}

__global__ void __launch_bounds__(256)
scan_prop(const float* __restrict__ Alog,
          const float* __restrict__ hloc, const float* __restrict__ Ssum,
          float* __restrict__ hin)
{
    int ch = blockIdx.x * blockDim.x + threadIdx.x;
    if (ch >= NCH) return;
    int d = ch & (DINNER - 1);

    float a[DSTATE];
#pragma unroll
    for (int n = 0; n < DSTATE; n++) a[n] = -__expf(Alog[d * DSTATE + n]);

    float h[DSTATE];
#pragma unroll
    for (int n = 0; n < DSTATE; n++) h[n] = 0.f;

    for (int s = 0; s < NSEG; s++) {
#pragma unroll
        for (int n = 0; n < DSTATE; n++)
            hin[((size_t)s * NCH + ch) * DSTATE + n] = h[n];
        float S = Ssum[(size_t)s * NCH + ch];
#pragma unroll
        for (int n = 0; n < DSTATE; n++)
            h[n] = __expf(a[n] * S) * h[n] + hloc[((size_t)s * NCH + ch) * DSTATE + n];
    }
}

// ---------------- launch -----------------------------------------------------
extern "C" void kernel_launch(void* const* d_in, const int* in_sizes, int n_in,
                              void* d_out, int out_size)
{
    (void)in_sizes; (void)n_in; (void)out_size;
    const float* x    = (const float*)d_in[0];
    const float* ipw  = (const float*)d_in[1];
    const float* ipb  = (const float*)d_in[2];
    const float* cw   = (const float*)d_in[3];
    const float* cb   = (const float*)d_in[4];
    const float* xpw  = (const float*)d_in[5];
    const float* dpw  = (const float*)d_in[6];
    const float* dpb  = (const float*)d_in[7];
    const float* alog = (const float*)d_in[8];
    const float* dvec = (const float*)d_in[9];
    const float* opw  = (const float*)d_in[10];
    const float* opb  = (const float*)d_in[11];
    float* out = (float*)d_out;

    float *xr, *xc, *xdbl, *dlt, *z, *xt, *ipt, *xpt, *dpt, *opt, *hloc, *Ss, *hin;
    cudaGetSymbolAddress((void**)&xr,   g_xr);
    cudaGetSymbolAddress((void**)&xc,   g_xc);
    cudaGetSymbolAddress((void**)&xdbl, g_xdbl);
    cudaGetSymbolAddress((void**)&dlt,  g_dlt);
    cudaGetSymbolAddress((void**)&z,    g_z);
    cudaGetSymbolAddress((void**)&xt,   g_xt);
    cudaGetSymbolAddress((void**)&ipt,  g_ipt);
    cudaGetSymbolAddress((void**)&xpt,  g_xpt);
    cudaGetSymbolAddress((void**)&dpt,  g_dpt);
    cudaGetSymbolAddress((void**)&opt,  g_opt);
    cudaGetSymbolAddress((void**)&hloc, g_hloc);
    cudaGetSymbolAddress((void**)&Ss,   g_S);
    cudaGetSymbolAddress((void**)&hin,  g_hin);

    constexpr int SM128 = 2 * (128 * 144 + 128 * 144);  // 73728 -> 2 blocks/SM
    constexpr int SM32  = 2 * (128 * 144 + 32 * 144);   // 46080
    constexpr int SMEM_SCAN = (6 * ST * 64 + 2 * ST * 32) * 4; // 114688
    cudaFuncSetAttribute((const void*)gemm_tf<128,128,2,4,0,0>, cudaFuncAttributeMaxDynamicSharedMemorySize, SM128);
    cudaFuncSetAttribute((const void*)gemm_tf<128,128,2,4,1,0>, cudaFuncAttributeMaxDynamicSharedMemorySize, SM128);
    cudaFuncSetAttribute((const void*)gemm_tf<128,32,8,1,0,1>,  cudaFuncAttributeMaxDynamicSharedMemorySize, SM32);
    cudaFuncSetAttribute((const void*)scan_seg<1>, cudaFuncAttributeMaxDynamicSharedMemorySize, SMEM_SCAN);
    cudaFuncSetAttribute((const void*)scan_seg<3>, cudaFuncAttributeMaxDynamicSharedMemorySize, SMEM_SCAN);

    round_k<<<(MTOT*DMODEL/4+255)/256, 256>>>((const float4*)x, (float4*)xt, MTOT*DMODEL/4);        // 0
    round_k<<<(2*DINNER*DMODEL/4+255)/256, 256>>>((const float4*)ipw, (float4*)ipt, 2*DINNER*DMODEL/4); // 1
    round_k<<<(XPDIM*DINNER/4+255)/256, 256>>>((const float4*)xpw, (float4*)xpt, XPDIM*DINNER/4);   // 2

    // in_proj (PROFILED @ index 3)                                             // 3
    gemm_tf<128,128,2,4,0,0><<<dim3(2*DINNER/128, MTOT/128), 256, SM128>>>(
        xt, DMODEL, ipt, DMODEL, xr, 2*DINNER, ipb, DMODEL);

    conv_k<<<MTOT, 256>>>(xr, cw, cb, xc);                                      // 4
    round_k<<<(DINNER*DTRANK/4+255)/256, 256>>>((const float4*)dpw, (float4*)dpt, DINNER*DTRANK/4); // 5

    // x_proj                                                                   // 6
    gemm_tf<128,32,8,1,0,1><<<dim3(XPDIM/32, MTOT/128), 256, SM32>>>(
        xc, DINNER, xpt, DINNER, xdbl, XPDIM, nullptr, DINNER);

    // dt_proj + softplus                                                       // 7
    gemm_tf<128,128,2,4,1,0><<<dim3(DINNER/128, MTOT/128), 256, SM128>>>(
        xdbl, XPDIM, dpt, DTRANK, dlt, DINNER, dpb, DTRANK);

    round_k<<<(DMODEL*DINNER/4+255)/256, 256>>>((const float4*)opw, (float4*)opt, DMODEL*DINNER/4); // 8

    // segmented scan: pass1 -> pass2 -> pass3
    scan_seg<1><<<NSEG * 128, SCD, SMEM_SCAN>>>(xdbl, dlt, xc, xr, alog, dvec,
                                                z, hloc, Ss, nullptr);          // 9
    scan_prop<<<NCH / 256, 256>>>(alog, hloc, Ss, hin);                         // 10
    scan_seg<3><<<NSEG * 128, SCD, SMEM_SCAN>>>(xdbl, dlt, xc, xr, alog, dvec,
                                                z, nullptr, nullptr, hin);      // 11

    // out_proj                                                                 // 12
    gemm_tf<128,128,2,4,0,0><<<dim3(DMODEL/128, MTOT/128), 256, SM128>>>(
        z, DINNER, opt, DINNER, out, DMODEL, opb, DINNER);
}

// round 17
// speedup vs baseline: 1.3412x; 1.0929x over previous
#include <cuda_runtime.h>
#include <cuda_bf16.h>
#include <cstdint>
#include <math.h>

#define BB 4
#define LSEQ 2048
#define DMODEL 1024
#define DINNER 2048
#define DSTATE 16
#define DTRANK 128
#define XPDIM 160
#define MTOT (BB*LSEQ)      // 8192
#define NSEG 8
#define SEGLEN (LSEQ/NSEG)  // 256
#define NCH (BB*DINNER)     // 8192 channels

// ---------------- scratch ----------------------------------------------------
static __device__ float g_xr  [(size_t)MTOT * 2 * DINNER];
static __device__ float g_xc  [(size_t)MTOT * DINNER];
static __device__ float g_xdbl[(size_t)MTOT * XPDIM];
static __device__ float g_dlt [(size_t)MTOT * DINNER];
static __device__ float g_z   [(size_t)MTOT * DINNER];
static __device__ float g_xt  [(size_t)MTOT * DMODEL];
static __device__ float g_ipt [(size_t)2*DINNER * DMODEL];
static __device__ float g_xpt [(size_t)XPDIM * DINNER];
static __device__ float g_dpt [(size_t)DINNER * DTRANK];
static __device__ float g_opt [(size_t)DMODEL * DINNER];
static __device__ float g_hloc[(size_t)NSEG * NCH * DSTATE];
static __device__ float g_S   [(size_t)NSEG * NCH];
static __device__ float g_hin [(size_t)NSEG * NCH * DSTATE];

// ---------------- PTX helpers ------------------------------------------------
__device__ __forceinline__ uint32_t smem_u32(const void* p) {
    uint32_t a;
    asm("{ .reg .u64 t; cvta.to.shared.u64 t, %1; cvt.u32.u64 %0, t; }" : "=r"(a) : "l"(p));
    return a;
}
__device__ __forceinline__ void cpa16(uint32_t s, const void* g) {
    asm volatile("cp.async.cg.shared.global [%0], [%1], 16;" :: "r"(s), "l"(g));
}
#define CP_COMMIT() asm volatile("cp.async.commit_group;" ::: "memory")
#define CP_WAIT(n)  asm volatile("cp.async.wait_group %0;" :: "n"(n) : "memory")

__device__ __forceinline__ void ldsm4(uint32_t* r, uint32_t a) {
    asm volatile("ldmatrix.sync.aligned.m8n8.x4.shared.b16 {%0,%1,%2,%3}, [%4];"
                 : "=r"(r[0]), "=r"(r[1]), "=r"(r[2]), "=r"(r[3]) : "r"(a));
}
__device__ __forceinline__ void ldsm2(uint32_t* r, uint32_t a) {
    asm volatile("ldmatrix.sync.aligned.m8n8.x2.shared.b16 {%0,%1}, [%2];"
                 : "=r"(r[0]), "=r"(r[1]) : "r"(a));
}
__device__ __forceinline__ void mma1688(float* d, const uint32_t* a, const uint32_t* b) {
    asm volatile(
        "mma.sync.aligned.m16n8k8.row.col.f32.tf32.tf32.f32 "
        "{%0,%1,%2,%3}, {%4,%5,%6,%7}, {%8,%9}, {%0,%1,%2,%3};"
        : "+f"(d[0]), "+f"(d[1]), "+f"(d[2]), "+f"(d[3])
        : "r"(a[0]), "r"(a[1]), "r"(a[2]), "r"(a[3]), "r"(b[0]), "r"(b[1]));
}
__device__ __forceinline__ float rtf(float v) {
    uint32_t r;
    asm("cvt.rna.tf32.f32 %0, %1;" : "=r"(r) : "f"(v));
    return __uint_as_float(r);
}

__global__ void round_k(const float4* __restrict__ in, float4* __restrict__ out, int n4) {
    int i = blockIdx.x * blockDim.x + threadIdx.x;
    if (i < n4) {
        float4 v = in[i];
        v.x = rtf(v.x); v.y = rtf(v.y); v.z = rtf(v.z); v.w = rtf(v.w);
        out[i] = v;
    }
}

// ---------------- tf32 HMMA GEMM (R16-proven, FROZEN) ------------------------
template<int BM, int BN, int WARPS_M, int WARPS_N, int EPI, int RND>
__global__ void __launch_bounds__(WARPS_M * WARPS_N * 32)
gemm_tf(const float* __restrict__ A, int lda,
        const float* __restrict__ B, int ldb,
        float* __restrict__ C, int ldc, const float* __restrict__ bias, int K)
{
    constexpr int NT = WARPS_M * WARPS_N * 32;
    constexpr int RS = 144;
    constexpr int SA = BM * RS;
    constexpr int SB = BN * RS;
    constexpr int STAGE = SA + SB;
    constexpr int WM = BM / WARPS_M, WN = BN / WARPS_N;
    constexpr int IM = WM / 16, JN = WN / 8;

    extern __shared__ char smem[];
    const uint32_t sbase = smem_u32(smem);
    const int tid = threadIdx.x;
    const int warp = tid >> 5, lane = tid & 31;
    const int wm0 = (warp / WARPS_N) * WM;
    const int wn0 = (warp % WARPS_N) * WN;
    const int m0 = blockIdx.y * BM, n0 = blockIdx.x * BN;
    const int NCC = K >> 5;

    float acc[IM][JN][4];
#pragma unroll
    for (int i = 0; i < IM; i++)
#pragma unroll
        for (int j = 0; j < JN; j++)
#pragma unroll
            for (int q = 0; q < 4; q++) acc[i][j][q] = 0.f;

    auto load_chunk = [&](int kc, int buf) {
        const int k0 = kc << 5;
        const uint32_t st = sbase + buf * STAGE;
        for (int idx = tid; idx < BM * 8; idx += NT) {
            int r = idx >> 3, c = idx & 7;
            cpa16(st + (uint32_t)(r * RS + c * 16), A + (size_t)(m0 + r) * lda + k0 + c * 4);
        }
        for (int idx = tid; idx < BN * 8; idx += NT) {
            int r = idx >> 3, c = idx & 7;
            cpa16(st + SA + (uint32_t)(r * RS + c * 16), B + (size_t)(n0 + r) * ldb + k0 + c * 4);
        }
        CP_COMMIT();
    };

    const uint32_t a_row  = (uint32_t)(wm0 + (lane & 15));
    const uint32_t a_half = (uint32_t)((lane >> 4) * 16);
    const uint32_t b_row  = (uint32_t)(wn0 + (lane & 7));
    const uint32_t b_half = (uint32_t)(((lane >> 3) & 1) * 16);

    load_chunk(0, 0);
    for (int i = 0; i < NCC; i++) {
        CP_WAIT(0);
        __syncthreads();
        if (i + 1 < NCC) load_chunk(i + 1, (i + 1) & 1);

        const uint32_t st = sbase + (i & 1) * STAGE;
        uint32_t af[2][IM][4], bf[2][JN][2];

        auto ldfrag = [&](int ks, int p) {
#pragma unroll
            for (int im = 0; im < IM; im++)
                ldsm4(af[p][im], st + (a_row + im * 16) * RS + ks * 32 + a_half);
#pragma unroll
            for (int jn = 0; jn < JN; jn++)
                ldsm2(bf[p][jn], st + SA + (b_row + jn * 8) * RS + ks * 32 + b_half);
        };

        ldfrag(0, 0);
#pragma unroll
        for (int ks = 0; ks < 4; ks++) {
            const int cur = ks & 1;
            if (ks < 3) ldfrag(ks + 1, cur ^ 1);
#pragma unroll
            for (int im = 0; im < IM; im++)
#pragma unroll
                for (int jn = 0; jn < JN; jn++)
                    mma1688(acc[im][jn], af[cur][im], bf[cur][jn]);
        }
    }

#pragma unroll
    for (int im = 0; im < IM; im++) {
#pragma unroll
        for (int jn = 0; jn < JN; jn++) {
            int r = m0 + wm0 + im * 16 + (lane >> 2);
            int c = n0 + wn0 + jn * 8 + (lane & 3) * 2;
#pragma unroll
            for (int half = 0; half < 2; half++) {
                int rr = r + half * 8;
                float t0 = acc[im][jn][half * 2 + 0];
                float t1 = acc[im][jn][half * 2 + 1];
                if (bias) { t0 += bias[c]; t1 += bias[c + 1]; }
                if (EPI == 1) {
                    t0 = fmaxf(t0, 0.f) + log1pf(expf(-fabsf(t0)));
                    t1 = fmaxf(t1, 0.f) + log1pf(expf(-fabsf(t1)));
                }
                if (RND) { t0 = rtf(t0); t1 = rtf(t1); }
                *(float2*)(C + (size_t)rr * ldc + c) = make_float2(t0, t1);
            }
        }
    }
}

// ---------------- depthwise conv1d ------------------------------------------
__global__ void __launch_bounds__(256)
conv_k(const float* __restrict__ xr, const float* __restrict__ w,
       const float* __restrict__ cb, float* __restrict__ out)
{
    const int m = blockIdx.x;
    const int t = m & (LSEQ - 1);
    const size_t rowb = (size_t)m * (2 * DINNER);
    const bool hm1 = (t >= 1), hp1 = (t <= LSEQ - 2), hp2 = (t <= LSEQ - 3);

#pragma unroll
    for (int g = 0; g < 2; g++) {
        const int d = (threadIdx.x + g * 256) * 4;
        float4 wv0 = *(const float4*)(w + (size_t)(d + 0) * 4);
        float4 wv1 = *(const float4*)(w + (size_t)(d + 1) * 4);
        float4 wv2 = *(const float4*)(w + (size_t)(d + 2) * 4);
        float4 wv3 = *(const float4*)(w + (size_t)(d + 3) * 4);
        float4 bv = *(const float4*)(cb + d);

        float4 xm1 = hm1 ? *(const float4*)(xr + rowb - 2 * DINNER + d) : make_float4(0,0,0,0);
        float4 x0  = *(const float4*)(xr + rowb + d);
        float4 xp1 = hp1 ? *(const float4*)(xr + rowb + 2 * DINNER + d) : make_float4(0,0,0,0);
        float4 xp2 = hp2 ? *(const float4*)(xr + rowb + 4 * DINNER + d) : make_float4(0,0,0,0);

        float4 o;
        o.x = rtf(bv.x + wv0.x * xm1.x + wv0.y * x0.x + wv0.z * xp1.x + wv0.w * xp2.x);
        o.y = rtf(bv.y + wv1.x * xm1.y + wv1.y * x0.y + wv1.z * xp1.y + wv1.w * xp2.y);
        o.z = rtf(bv.z + wv2.x * xm1.z + wv2.y * x0.z + wv2.z * xp1.z + wv2.w * xp2.z);
        o.w = rtf(bv.w + wv3.x * xm1.w + wv3.y * x0.w + wv3.z * xp1.w + wv3.w * xp2.w);
        *(float4*)(out + (size_t)m * DINNER + d) = o;
    }
}

// ---------------- segmented selective scan -----------------------------------
// ST=32, SCD=128: 128-thread blocks, 104 KB smem -> 2 blocks/SM (8 warps/SM,
// 4x the per-SM parallelism of the old 64-thread/114KB config). Same math.
#define ST 32
#define SCD 128
template<int PASS>
__global__ void __launch_bounds__(SCD)
scan_seg(const float* __restrict__ xdbl, const float* __restrict__ delta,
         const float* __restrict__ u, const float* __restrict__ xr,
         const float* __restrict__ Alog, const float* __restrict__ Dp,
         float* __restrict__ z,
         float* __restrict__ hloc, float* __restrict__ Ssum,
         const float* __restrict__ hin)
{
    extern __shared__ float sm[];
    float* sD  = sm;                     // [2][ST*SCD]
    float* sU  = sm + 2 * ST * SCD;
    float* sR  = sm + 4 * ST * SCD;      // staged only in PASS 3
    float* sBC = sm + 6 * ST * SCD;      // [2][ST*32]
    const uint32_t sbase = smem_u32(sm);

    const int tid = threadIdx.x;
    const int s   = blockIdx.x >> 6;             // segment 0..7 (64 blocks/segment)
    const int rem = blockIdx.x & 63;
    const int b   = rem >> 4;                    // batch 0..3 (16 d-blocks/batch)
    const int d0  = (rem & 15) * SCD;
    const int d   = d0 + tid;
    const int ch  = b * DINNER + d;

    float a[DSTATE];
#pragma unroll
    for (int n = 0; n < DSTATE; n++) a[n] = -__expf(Alog[d * DSTATE + n]);
    bool geo = true;
#pragma unroll
    for (int n = 1; n < DSTATE; n++)
        geo = geo && (fabsf(a[n] - (float)(n + 1) * a[0]) <= 1e-4f * (float)(n + 1) * fabsf(a[0]));

    const float dd = Dp[d];
    float h[DSTATE];
    if (PASS == 3) {
#pragma unroll
        for (int n = 0; n < DSTATE; n++) h[n] = hin[((size_t)s * NCH + ch) * DSTATE + n];
    } else {
#pragma unroll
        for (int n = 0; n < DSTATE; n++) h[n] = 0.f;
    }
    float S = 0.f;

    auto stage = [&](int c, int bufi) {
        const int t0 = s * SEGLEN + c * ST;
        for (int i = tid; i < ST * (SCD / 4); i += SCD) {     // 32 rows x 32 f4
            int t = i >> 5, q = i & 31;
            size_t m = (size_t)(b * LSEQ + t0 + t);
            uint32_t so = (uint32_t)((bufi * ST * SCD + t * SCD + q * 4) * 4);
            cpa16(sbase + so, delta + m * DINNER + d0 + q * 4);
            cpa16(sbase + 2 * ST * SCD * 4 + so, u + m * DINNER + d0 + q * 4);
            if (PASS == 3)
                cpa16(sbase + 4 * ST * SCD * 4 + so, xr + m * (2 * DINNER) + DINNER + d0 + q * 4);
        }
        for (int i = tid; i < ST * 8; i += SCD) {             // BC: 32 rows x 8 f4
            int t = i >> 3, q = i & 7;
            uint32_t so = (uint32_t)(6 * ST * SCD * 4 + (bufi * ST * 32 + t * 32 + q * 4) * 4);
            cpa16(sbase + so, xdbl + (size_t)(b * LSEQ + t0 + t) * XPDIM + DTRANK + q * 4);
        }
        CP_COMMIT();
    };

    const int NCHK = SEGLEN / ST;   // 8
    stage(0, 0);
    for (int c = 0; c < NCHK; c++) {
        const int bufi = c & 1;
        if (c + 1 < NCHK) { stage(c + 1, (c + 1) & 1); CP_WAIT(1); }
        else              { CP_WAIT(0); }
        __syncthreads();

        const float* pD  = sD  + bufi * ST * SCD;
        const float* pU  = sU  + bufi * ST * SCD;
        const float* pR  = sR  + bufi * ST * SCD;
        const float* pBC = sBC + bufi * ST * 32;

        for (int tt = 0; tt < ST; tt++) {
            float dlt = pD[tt * SCD + tid];
            float uu  = pU[tt * SCD + tid];
            float du = dlt * uu;
            if (PASS == 1) S += dlt;

            float bv[DSTATE], cv[DSTATE];
#pragma unroll
            for (int q = 0; q < 4; q++) {
                float4 vb = *(const float4*)(pBC + tt * 32 + q * 4);
                bv[q*4+0]=vb.x; bv[q*4+1]=vb.y; bv[q*4+2]=vb.z; bv[q*4+3]=vb.w;
                float4 vc = *(const float4*)(pBC + tt * 32 + 16 + q * 4);
                cv[q*4+0]=vc.x; cv[q*4+1]=vc.y; cv[q*4+2]=vc.z; cv[q*4+3]=vc.w;
            }

            float y0 = 0.f, y1 = 0.f, y2 = 0.f, y3 = 0.f;
            if (geo) {
                float p[DSTATE];
                p[0] = __expf(dlt * a[0]);
#pragma unroll
                for (int n = 1; n < DSTATE; n++) p[n] = p[(n - 1) >> 1] * p[n >> 1];
#pragma unroll
                for (int n = 0; n < DSTATE; n++) {
                    h[n] = p[n] * h[n] + du * bv[n];
                    if (PASS == 3) {
                        float t = h[n] * cv[n];
                        if ((n & 3) == 0) y0 += t; else if ((n & 3) == 1) y1 += t;
                        else if ((n & 3) == 2) y2 += t; else y3 += t;
                    }
                }
            } else {
#pragma unroll
                for (int n = 0; n < DSTATE; n++) {
                    float dA = __expf(dlt * a[n]);
                    h[n] = dA * h[n] + du * bv[n];
                    if (PASS == 3) {
                        float t = h[n] * cv[n];
                        if ((n & 3) == 0) y0 += t; else if ((n & 3) == 1) y1 += t;
                        else if ((n & 3) == 2) y2 += t; else y3 += t;
                    }
                }
            }

            if (PASS == 3) {
                float y = (y0 + y1) + (y2 + y3) + uu * dd;
                float rr = pR[tt * SCD + tid];
                float sg = 1.f / (1.f + __expf(-rr));
                size_t m = (size_t)(b * LSEQ + s * SEGLEN + c * ST + tt);
                z[m * DINNER + d] = rtf(y * (rr * sg));
            }
        }
        __syncthreads();
    }

    if (PASS == 1) {
#pragma unroll
        for (int n = 0; n < DSTATE; n++)
            hloc[((size_t)s * NCH + ch) * DSTATE + n] = h[n];
        Ssum[(size_t)s * NCH + ch] = S;
    }
}

__global__ void __launch_bounds__(256)
scan_prop(const float* __restrict__ Alog,
          const float* __restrict__ hloc, const float* __restrict__ Ssum,
          float* __restrict__ hin)
{
    int ch = blockIdx.x * blockDim.x + threadIdx.x;
    if (ch >= NCH) return;
    int d = ch & (DINNER - 1);

    float a[DSTATE];
#pragma unroll
    for (int n = 0; n < DSTATE; n++) a[n] = -__expf(Alog[d * DSTATE + n]);

    float h[DSTATE];
#pragma unroll
    for (int n = 0; n < DSTATE; n++) h[n] = 0.f;

    for (int s = 0; s < NSEG; s++) {
#pragma unroll
        for (int n = 0; n < DSTATE; n++)
            hin[((size_t)s * NCH + ch) * DSTATE + n] = h[n];
        float S = Ssum[(size_t)s * NCH + ch];
#pragma unroll
        for (int n = 0; n < DSTATE; n++)
            h[n] = __expf(a[n] * S) * h[n] + hloc[((size_t)s * NCH + ch) * DSTATE + n];
    }
}

// ---------------- launch -----------------------------------------------------
extern "C" void kernel_launch(void* const* d_in, const int* in_sizes, int n_in,
                              void* d_out, int out_size)
{
    (void)in_sizes; (void)n_in; (void)out_size;
    const float* x    = (const float*)d_in[0];
    const float* ipw  = (const float*)d_in[1];
    const float* ipb  = (const float*)d_in[2];
    const float* cw   = (const float*)d_in[3];
    const float* cb   = (const float*)d_in[4];
    const float* xpw  = (const float*)d_in[5];
    const float* dpw  = (const float*)d_in[6];
    const float* dpb  = (const float*)d_in[7];
    const float* alog = (const float*)d_in[8];
    const float* dvec = (const float*)d_in[9];
    const float* opw  = (const float*)d_in[10];
    const float* opb  = (const float*)d_in[11];
    float* out = (float*)d_out;

    float *xr, *xc, *xdbl, *dlt, *z, *xt, *ipt, *xpt, *dpt, *opt, *hloc, *Ss, *hin;
    cudaGetSymbolAddress((void**)&xr,   g_xr);
    cudaGetSymbolAddress((void**)&xc,   g_xc);
    cudaGetSymbolAddress((void**)&xdbl, g_xdbl);
    cudaGetSymbolAddress((void**)&dlt,  g_dlt);
    cudaGetSymbolAddress((void**)&z,    g_z);
    cudaGetSymbolAddress((void**)&xt,   g_xt);
    cudaGetSymbolAddress((void**)&ipt,  g_ipt);
    cudaGetSymbolAddress((void**)&xpt,  g_xpt);
    cudaGetSymbolAddress((void**)&dpt,  g_dpt);
    cudaGetSymbolAddress((void**)&opt,  g_opt);
    cudaGetSymbolAddress((void**)&hloc, g_hloc);
    cudaGetSymbolAddress((void**)&Ss,   g_S);
    cudaGetSymbolAddress((void**)&hin,  g_hin);

    constexpr int SM128 = 2 * (128 * 144 + 128 * 144);  // 73728
    constexpr int SM32  = 2 * (128 * 144 + 32 * 144);   // 46080
    constexpr int SMEM_SCAN = (6 * ST * SCD + 2 * ST * 32) * 4; // 106496
    cudaFuncSetAttribute((const void*)gemm_tf<128,128,2,4,0,0>, cudaFuncAttributeMaxDynamicSharedMemorySize, SM128);
    cudaFuncSetAttribute((const void*)gemm_tf<128,128,2,4,1,0>, cudaFuncAttributeMaxDynamicSharedMemorySize, SM128);
    cudaFuncSetAttribute((const void*)gemm_tf<128,32,2,2,0,1>,  cudaFuncAttributeMaxDynamicSharedMemorySize, SM32);
    cudaFuncSetAttribute((const void*)scan_seg<1>, cudaFuncAttributeMaxDynamicSharedMemorySize, SMEM_SCAN);
    cudaFuncSetAttribute((const void*)scan_seg<3>, cudaFuncAttributeMaxDynamicSharedMemorySize, SMEM_SCAN);

    round_k<<<(MTOT*DMODEL/4+255)/256, 256>>>((const float4*)x, (float4*)xt, MTOT*DMODEL/4);        // 0
    round_k<<<(2*DINNER*DMODEL/4+255)/256, 256>>>((const float4*)ipw, (float4*)ipt, 2*DINNER*DMODEL/4); // 1
    round_k<<<(XPDIM*DINNER/4+255)/256, 256>>>((const float4*)xpw, (float4*)xpt, XPDIM*DINNER/4);   // 2

    // in_proj (PROFILED @ index 3, control)                                    // 3
    gemm_tf<128,128,2,4,0,0><<<dim3(2*DINNER/128, MTOT/128), 256, SM128>>>(
        xt, DMODEL, ipt, DMODEL, xr, 2*DINNER, ipb, DMODEL);

    conv_k<<<MTOT, 256>>>(xr, cw, cb, xc);                                      // 4
    round_k<<<(DINNER*DTRANK/4+255)/256, 256>>>((const float4*)dpw, (float4*)dpt, DINNER*DTRANK/4); // 5

    // x_proj: 128-thread <128,32,2,2> config (IM=4/JN=2, ratio 0.75)           // 6
    gemm_tf<128,32,2,2,0,1><<<dim3(XPDIM/32, MTOT/128), 128, SM32>>>(
        xc, DINNER, xpt, DINNER, xdbl, XPDIM, nullptr, DINNER);

    // dt_proj + softplus                                                       // 7
    gemm_tf<128,128,2,4,1,0><<<dim3(DINNER/128, MTOT/128), 256, SM128>>>(
        xdbl, XPDIM, dpt, DTRANK, dlt, DINNER, dpb, DTRANK);

    round_k<<<(DMODEL*DINNER/4+255)/256, 256>>>((const float4*)opw, (float4*)opt, DMODEL*DINNER/4); // 8

    // segmented scan (512 blocks x 128 threads per pass)
    scan_seg<1><<<NSEG * 64, SCD, SMEM_SCAN>>>(xdbl, dlt, xc, xr, alog, dvec,
                                               z, hloc, Ss, nullptr);           // 9
    scan_prop<<<NCH / 256, 256>>>(alog, hloc, Ss, hin);                         // 10
    scan_seg<3><<<NSEG * 64, SCD, SMEM_SCAN>>>(xdbl, dlt, xc, xr, alog, dvec,
                                               z, nullptr, nullptr, hin);       // 11

    // out_proj                                                                 // 12
    gemm_tf<128,128,2,4,0,0><<<dim3(DMODEL/128, MTOT/128), 256, SM128>>>(
        z, DINNER, opt, DINNER, out, DMODEL, opb, DINNER);
}